// round 8
// baseline (speedup 1.0000x reference)
#include <cuda_runtime.h>
#include <cuda_bf16.h>
#include <cstdint>

// ---------------------------------------------------------------------------
// TCNet: B=128, NV=100, NQ=14, NA=10, V_DIM=2048, Q_DIM=1024, A_DIM=1024,
//        H_DIM=512, RANK=32, HD=16, G=2
//
// einsum 'rijkg,bnvi,bnqj,bnak->bvqag' : r and n are INDEPENDENT sums.
//   Tbar[i,j,k,g] = sum_r T[r,i,j,k,g]
//   out[b,v,q,a,g] = sum_{n,i,j,k} Tbar v_ q_ a_
//
// All big GEMMs run on mma.sync bf16 (HMMA) with bf16x3 fp32 emulation:
// hi*hi + hi*lo + lo*hi.
// GEMM config: 256 threads (8 warps 4x2, warp tile 32x64), 2 CTAs/SM.
// ---------------------------------------------------------------------------

#define Bb    128
#define NV    100
#define NQ    14
#define NA    10
#define RANK  32
#define G     2
#define QAG   (NQ*NA*G)   // 280
#define CPAD  288         // padded TQA_T row count

// ---------------- scratch (static device globals, zero-initialized) --------
__device__ __align__(256) __nv_bfloat16 g_v_hi [12800*2048], g_v_lo [12800*2048];
__device__ __align__(256) __nv_bfloat16 g_q_hi [1792*1024],  g_q_lo [1792*1024];
__device__ __align__(256) __nv_bfloat16 g_a_hi [1280*1024],  g_a_lo [1280*1024];
__device__ __align__(256) __nv_bfloat16 g_Wv_hi[512*2048],   g_Wv_lo[512*2048];
__device__ __align__(256) __nv_bfloat16 g_Wq_hi[512*1024],   g_Wq_lo[512*1024];
__device__ __align__(256) __nv_bfloat16 g_Wa_hi[512*1024],   g_Wa_lo[512*1024];
__device__ __align__(256) __nv_bfloat16 g_Wvr_hi[512*512],   g_Wvr_lo[512*512];
__device__ __align__(256) __nv_bfloat16 g_Wqr_hi[512*512],   g_Wqr_lo[512*512];
__device__ __align__(256) __nv_bfloat16 g_War_hi[512*512],   g_War_lo[512*512];
__device__ __align__(256) __nv_bfloat16 g_vt_hi[12800*512],  g_vt_lo[12800*512];
__device__ __align__(256) __nv_bfloat16 g_qt_hi[1792*512],   g_qt_lo[1792*512];
__device__ __align__(256) __nv_bfloat16 g_at_hi[1280*512],   g_at_lo[1280*512];
__device__ __align__(256) __nv_bfloat16 g_v2_hi[12832*512],  g_v2_lo[12832*512];
__device__ __align__(256) float g_q2[1792*512];
__device__ __align__(256) float g_a2[1280*512];
__device__ __align__(256) __nv_bfloat16 g_tqaT_hi[128*CPAD*512];
__device__ __align__(256) __nv_bfloat16 g_tqaT_lo[128*CPAD*512];
__device__ __align__(256) float g_Tbar[8192];

// ---------------- PTX helpers ----------------
__device__ __forceinline__ uint32_t smem_u32(const void* p) {
    uint32_t a;
    asm("{ .reg .u64 t; cvta.to.shared.u64 t, %1; cvt.u32.u64 %0, t; }"
        : "=r"(a) : "l"(p));
    return a;
}
__device__ __forceinline__ void mma_bf16(float* c, const uint32_t* a,
                                         const uint32_t* b) {
    asm volatile(
        "mma.sync.aligned.m16n8k16.row.col.f32.bf16.bf16.f32 "
        "{%0,%1,%2,%3}, {%4,%5,%6,%7}, {%8,%9}, {%0,%1,%2,%3};"
        : "+f"(c[0]), "+f"(c[1]), "+f"(c[2]), "+f"(c[3])
        : "r"(a[0]), "r"(a[1]), "r"(a[2]), "r"(a[3]), "r"(b[0]), "r"(b[1]));
}
__device__ __forceinline__ void ldsm4(uint32_t* r, uint32_t addr) {
    asm volatile("ldmatrix.sync.aligned.m8n8.x4.shared.b16 {%0,%1,%2,%3}, [%4];"
                 : "=r"(r[0]), "=r"(r[1]), "=r"(r[2]), "=r"(r[3]) : "r"(addr));
}
__device__ __forceinline__ void cp16(uint32_t dst, const void* src) {
    asm volatile("cp.async.cg.shared.global [%0], [%1], 16;"
                 :: "r"(dst), "l"(src));
}
__device__ __forceinline__ void cp_commit() {
    asm volatile("cp.async.commit_group;");
}
template<int N>
__device__ __forceinline__ void cp_wait() {
    asm volatile("cp.async.wait_group %0;" :: "n"(N));
}
__device__ __forceinline__ uint32_t swz_off(int row, int c) {
    return (uint32_t)(row * 64 + ((c ^ ((row >> 1) & 3)) << 4));
}

// ---------------------------------------------------------------------------
// split fp32 -> bf16 hi/lo (8 elements per thread)
// ---------------------------------------------------------------------------
__global__ void split_bf16_kernel(const float* __restrict__ x,
                                  __nv_bfloat16* __restrict__ hi,
                                  __nv_bfloat16* __restrict__ lo, int n8)
{
    int i = blockIdx.x * 256 + threadIdx.x;
    if (i >= n8) return;
    float4 v0 = ((const float4*)x)[i * 2];
    float4 v1 = ((const float4*)x)[i * 2 + 1];
    float f[8] = {v0.x, v0.y, v0.z, v0.w, v1.x, v1.y, v1.z, v1.w};
    __nv_bfloat162 H[4], L[4];
    #pragma unroll
    for (int j = 0; j < 4; j++) {
        __nv_bfloat16 h0 = __float2bfloat16(f[j*2]);
        __nv_bfloat16 h1 = __float2bfloat16(f[j*2+1]);
        H[j] = {h0, h1};
        L[j] = {__float2bfloat16(f[j*2]   - __bfloat162float(h0)),
                __float2bfloat16(f[j*2+1] - __bfloat162float(h1))};
    }
    ((uint4*)hi)[i] = *(uint4*)H;
    ((uint4*)lo)[i] = *(uint4*)L;
}

// ---------------------------------------------------------------------------
// Tbar[x] = sum_r T[r*8192 + x]
// ---------------------------------------------------------------------------
__global__ void reduce_T_kernel(const float* __restrict__ T)
{
    int x = blockIdx.x * 256 + threadIdx.x;
    float s = 0.f;
    #pragma unroll
    for (int r = 0; r < RANK; r++) s += T[(size_t)r * 8192 + x];
    g_Tbar[x] = s;
}

// ---------------------------------------------------------------------------
// HMMA bf16x3 GEMM: C[m,n] = relu( sum_k A[m,k]*W[n,k] + bias[n] )
// BM=128, BN=128, BK=32, 256 threads (8 warps 4x2, warp tile 32x64),
// cp.async double buffer, 2 CTAs/SM.
// ---------------------------------------------------------------------------
#define STAGE_SZ 32768
#define GEMM_SMEM (2 * STAGE_SZ)
#define OFF_AH 0
#define OFF_AL 8192
#define OFF_BH 16384
#define OFF_BL 24576

template<int OUT_BF16>
__global__ __launch_bounds__(256, 2)
void mma_gemm(const __nv_bfloat16* __restrict__ Ahi,
              const __nv_bfloat16* __restrict__ Alo,
              const __nv_bfloat16* __restrict__ Bhi,
              const __nv_bfloat16* __restrict__ Blo,
              const float* __restrict__ bias,
              float* __restrict__ Cf,
              __nv_bfloat16* __restrict__ Chi,
              __nv_bfloat16* __restrict__ Clo,
              int M, int N, int K)
{
    extern __shared__ char smem[];
    const uint32_t smb = smem_u32(smem);
    const int tid  = threadIdx.x;
    const int wid  = tid >> 5;
    const int lane = tid & 31;
    const int wm   = wid & 3;          // 4 warps along M (32 rows)
    const int wn   = wid >> 2;         // 2 warps along N (64 cols)
    const int bm   = blockIdx.y * 128;
    const int bn   = blockIdx.x * 128;

    const int nchunks = K >> 5;

    auto load_stage = [&](int c) {
        const uint32_t sb = smb + (uint32_t)(c & 1) * STAGE_SZ;
        const int k0 = c << 5;
        #pragma unroll
        for (int i = 0; i < 2; i++) {
            int idx = tid + i * 256;         // 0..511
            int row = idx >> 2;
            int cc  = idx & 3;
            uint32_t so = swz_off(row, cc);
            size_t gA = (size_t)(bm + row) * K + k0 + cc * 8;
            size_t gB = (size_t)(bn + row) * K + k0 + cc * 8;
            cp16(sb + OFF_AH + so, Ahi + gA);
            cp16(sb + OFF_AL + so, Alo + gA);
            cp16(sb + OFF_BH + so, Bhi + gB);
            cp16(sb + OFF_BL + so, Blo + gB);
        }
    };

    float acc[2][8][4];
    #pragma unroll
    for (int mt = 0; mt < 2; mt++)
        #pragma unroll
        for (int nt = 0; nt < 8; nt++)
            #pragma unroll
            for (int i = 0; i < 4; i++) acc[mt][nt][i] = 0.f;

    const int a_r = (lane & 7) | (((lane >> 3) & 1) << 3);
    const int a_c = lane >> 4;
    const int b_r = (lane & 7) | ((lane >> 4) << 3);
    const int b_c = (lane >> 3) & 1;

    load_stage(0);
    cp_commit();

    for (int c = 0; c < nchunks; c++) {
        if (c + 1 < nchunks) {
            load_stage(c + 1);
            cp_commit();
            cp_wait<1>();
        } else {
            cp_wait<0>();
        }
        __syncthreads();

        const uint32_t sb = smb + (uint32_t)(c & 1) * STAGE_SZ;

        #pragma unroll
        for (int ks8 = 0; ks8 < 4; ks8 += 2) {
            uint32_t af_h[2][4], af_l[2][4];
            #pragma unroll
            for (int mt = 0; mt < 2; mt++) {
                int row = wm * 32 + mt * 16 + a_r;
                uint32_t so = swz_off(row, ks8 + a_c);
                ldsm4(af_h[mt], sb + OFF_AH + so);
                ldsm4(af_l[mt], sb + OFF_AL + so);
            }
            // per-nq B fragments (keeps register pressure low)
            #pragma unroll
            for (int nq = 0; nq < 4; nq++) {
                uint32_t bf_h[4], bf_l[4];
                int row = wn * 64 + nq * 16 + b_r;
                uint32_t so = swz_off(row, ks8 + b_c);
                ldsm4(bf_h, sb + OFF_BH + so);
                ldsm4(bf_l, sb + OFF_BL + so);
                #pragma unroll
                for (int mt = 0; mt < 2; mt++)
                    #pragma unroll
                    for (int h = 0; h < 2; h++) {
                        float* ac = acc[mt][nq * 2 + h];
                        mma_bf16(ac, af_h[mt], &bf_h[h * 2]);
                        mma_bf16(ac, af_h[mt], &bf_l[h * 2]);
                        mma_bf16(ac, af_l[mt], &bf_h[h * 2]);
                    }
            }
        }
        __syncthreads();
    }

    // epilogue: bias + relu
    const int g = lane >> 2;
    const int t = lane & 3;
    #pragma unroll
    for (int mt = 0; mt < 2; mt++) {
        #pragma unroll
        for (int nt = 0; nt < 8; nt++) {
            int row0 = bm + wm * 32 + mt * 16 + g;
            int row1 = row0 + 8;
            int col  = bn + wn * 64 + nt * 8 + t * 2;
            float bs0 = __ldg(bias + col), bs1 = __ldg(bias + col + 1);
            float v00 = fmaxf(acc[mt][nt][0] + bs0, 0.f);
            float v01 = fmaxf(acc[mt][nt][1] + bs1, 0.f);
            float v10 = fmaxf(acc[mt][nt][2] + bs0, 0.f);
            float v11 = fmaxf(acc[mt][nt][3] + bs1, 0.f);
            if (OUT_BF16) {
                __nv_bfloat16 h00 = __float2bfloat16(v00);
                __nv_bfloat16 h01 = __float2bfloat16(v01);
                __nv_bfloat16 h10 = __float2bfloat16(v10);
                __nv_bfloat16 h11 = __float2bfloat16(v11);
                __nv_bfloat162 H0 = {h00, h01}, H1 = {h10, h11};
                __nv_bfloat162 L0 = {
                    __float2bfloat16(v00 - __bfloat162float(h00)),
                    __float2bfloat16(v01 - __bfloat162float(h01))};
                __nv_bfloat162 L1 = {
                    __float2bfloat16(v10 - __bfloat162float(h10)),
                    __float2bfloat16(v11 - __bfloat162float(h11))};
                *(__nv_bfloat162*)(Chi + (size_t)row0 * N + col) = H0;
                *(__nv_bfloat162*)(Clo + (size_t)row0 * N + col) = L0;
                *(__nv_bfloat162*)(Chi + (size_t)row1 * N + col) = H1;
                *(__nv_bfloat162*)(Clo + (size_t)row1 * N + col) = L1;
            } else {
                *(float2*)(Cf + (size_t)row0 * N + col) = make_float2(v00, v01);
                *(float2*)(Cf + (size_t)row1 * N + col) = make_float2(v10, v11);
            }
        }
    }
}

// ---------------------------------------------------------------------------
// K7: per (b,n):  Tq = Tbar x_j q_,  Tqa = Tq x_k a_
// Writes TQA transposed as bf16 hi/lo: g_tqaT[b][c][n*16+ii], c=(q*10+a)*2+g
// ---------------------------------------------------------------------------
__global__ __launch_bounds__(256)
void tq_tqa_kernel()
{
    extern __shared__ float sm[];
    float* sT  = sm;               // 8192 (reused as sOut after step A)
    float* sQ  = sm + 8192;        // 224
    float* sA  = sm + 8416;        // 160
    float* sTq = sm + 8576;        // 7168

    const int n   = blockIdx.x;
    const int b   = blockIdx.y;
    const int tid = threadIdx.x;

    const float4* Tp = (const float4*)g_Tbar;
    for (int i = tid; i < 2048; i += 256) ((float4*)sT)[i] = Tp[i];

    if (tid < 56) {
        int q  = tid >> 2;
        int j4 = (tid & 3) << 2;
        *(float4*)&sQ[q * 16 + j4] =
            *(const float4*)(g_q2 + (size_t)(b * NQ + q) * 512 + n * 16 + j4);
    }
    if (tid >= 64 && tid < 104) {
        int t  = tid - 64;
        int a  = t >> 2;
        int k4 = (t & 3) << 2;
        *(float4*)&sA[a * 16 + k4] =
            *(const float4*)(g_a2 + (size_t)(b * NA + a) * 512 + n * 16 + k4);
    }
    __syncthreads();

    // step A: Tq[q,i,k,g]
    {
        const int i_ = tid >> 4;
        const int k_ = tid & 15;
        float accx[14], accy[14];
        #pragma unroll
        for (int q = 0; q < 14; q++) { accx[q] = 0.f; accy[q] = 0.f; }
        #pragma unroll
        for (int j = 0; j < 16; j++) {
            float2 t2 = *(const float2*)&sT[(((i_ * 16 + j) * 16) + k_) * 2];
            #pragma unroll
            for (int q = 0; q < 14; q++) {
                float qv = sQ[q * 16 + j];
                accx[q] = fmaf(t2.x, qv, accx[q]);
                accy[q] = fmaf(t2.y, qv, accy[q]);
            }
        }
        #pragma unroll
        for (int q = 0; q < 14; q++)
            *(float2*)&sTq[((q * 16 + i_) * 16 + k_) * 2] =
                make_float2(accx[q], accy[q]);
    }
    __syncthreads();

    // step B: contract with a_, stash transposed in sOut[ii][c]
    float* sOut = sT;   // [16][284]
    for (int t = tid; t < 2240; t += 256) {
        int ii  = t / 140;
        int rem = t - ii * 140;
        int q   = rem / 10;
        int a   = rem - q * 10;
        float sx = 0.f, sy = 0.f;
        #pragma unroll
        for (int k = 0; k < 16; k++) {
            float2 tq = *(const float2*)&sTq[((q * 16 + ii) * 16 + k) * 2];
            float  av = sA[a * 16 + k];
            sx = fmaf(tq.x, av, sx);
            sy = fmaf(tq.y, av, sy);
        }
        sOut[ii * 284 + rem * 2]     = sx;
        sOut[ii * 284 + rem * 2 + 1] = sy;
    }
    __syncthreads();

    for (int idx = tid; idx < 560; idx += 256) {
        int c    = idx >> 1;
        int half = idx & 1;
        __nv_bfloat162 H[4], L[4];
        #pragma unroll
        for (int j = 0; j < 4; j++) {
            float v0 = sOut[(half * 8 + j * 2)     * 284 + c];
            float v1 = sOut[(half * 8 + j * 2 + 1) * 284 + c];
            __nv_bfloat16 h0 = __float2bfloat16(v0);
            __nv_bfloat16 h1 = __float2bfloat16(v1);
            H[j] = {h0, h1};
            L[j] = {__float2bfloat16(v0 - __bfloat162float(h0)),
                    __float2bfloat16(v1 - __bfloat162float(h1))};
        }
        size_t off = ((size_t)b * CPAD + c) * 512 + n * 16 + half * 8;
        *(uint4*)(g_tqaT_hi + off) = *(uint4*)H;
        *(uint4*)(g_tqaT_lo + off) = *(uint4*)L;
    }
}

// ---------------------------------------------------------------------------
// K8 (HMMA): out[b][v][c] = sum_k V2[b*100+v][k] * TQA_T[b][c][k]
// BM=128 (100 valid), BN=96, BK=32, 256 threads (8 warps 4x2, warp 32x48).
// ---------------------------------------------------------------------------
#define K8_STAGE 28672
#define K8_SMEM  (2 * K8_STAGE)
#define K8_BH    16384
#define K8_BL    22528

__global__ __launch_bounds__(256, 2)
void k8_gemm(float* __restrict__ out)
{
    extern __shared__ char smem[];
    const uint32_t smb = smem_u32(smem);
    const int tid  = threadIdx.x;
    const int wid  = tid >> 5;
    const int lane = tid & 31;
    const int wm   = wid & 3;
    const int wn   = wid >> 2;
    const int bn   = blockIdx.x * 96;
    const int b    = blockIdx.y;

    const __nv_bfloat16* Ahi = g_v2_hi + (size_t)b * 100 * 512;
    const __nv_bfloat16* Alo = g_v2_lo + (size_t)b * 100 * 512;
    const __nv_bfloat16* Bhi = g_tqaT_hi + ((size_t)b * CPAD + bn) * 512;
    const __nv_bfloat16* Blo = g_tqaT_lo + ((size_t)b * CPAD + bn) * 512;

    auto load_stage = [&](int c) {
        const uint32_t sb = smb + (uint32_t)(c & 1) * K8_STAGE;
        const int k0 = c << 5;
        #pragma unroll
        for (int i = 0; i < 2; i++) {
            int idx = tid + i * 256;
            int row = idx >> 2, cc = idx & 3;
            uint32_t so = swz_off(row, cc);
            size_t g = (size_t)row * 512 + k0 + cc * 8;
            cp16(sb + OFF_AH + so, Ahi + g);
            cp16(sb + OFF_AL + so, Alo + g);
        }
        {
            int idx = tid;
            int row = idx >> 2, cc = idx & 3;
            uint32_t so = swz_off(row, cc);
            size_t g = (size_t)row * 512 + k0 + cc * 8;
            cp16(sb + K8_BH + so, Bhi + g);
            cp16(sb + K8_BL + so, Blo + g);
        }
        if (tid < 128) {
            int idx = tid + 256;
            int row = idx >> 2, cc = idx & 3;
            uint32_t so = swz_off(row, cc);
            size_t g = (size_t)row * 512 + k0 + cc * 8;
            cp16(sb + K8_BH + so, Bhi + g);
            cp16(sb + K8_BL + so, Blo + g);
        }
    };

    float acc[2][6][4];
    #pragma unroll
    for (int mt = 0; mt < 2; mt++)
        #pragma unroll
        for (int nt = 0; nt < 6; nt++)
            #pragma unroll
            for (int i = 0; i < 4; i++) acc[mt][nt][i] = 0.f;

    const int a_r = (lane & 7) | (((lane >> 3) & 1) << 3);
    const int a_c = lane >> 4;
    const int b_r = (lane & 7) | ((lane >> 4) << 3);
    const int b_c = (lane >> 3) & 1;

    load_stage(0);
    cp_commit();

    for (int c = 0; c < 16; c++) {
        if (c + 1 < 16) {
            load_stage(c + 1);
            cp_commit();
            cp_wait<1>();
        } else {
            cp_wait<0>();
        }
        __syncthreads();

        const uint32_t sb = smb + (uint32_t)(c & 1) * K8_STAGE;

        #pragma unroll
        for (int ks8 = 0; ks8 < 4; ks8 += 2) {
            uint32_t af_h[2][4], af_l[2][4];
            #pragma unroll
            for (int mt = 0; mt < 2; mt++) {
                int row = wm * 32 + mt * 16 + a_r;
                uint32_t so = swz_off(row, ks8 + a_c);
                ldsm4(af_h[mt], sb + OFF_AH + so);
                ldsm4(af_l[mt], sb + OFF_AL + so);
            }
            #pragma unroll
            for (int nq = 0; nq < 3; nq++) {
                uint32_t bf_h[4], bf_l[4];
                int row = wn * 48 + nq * 16 + b_r;
                uint32_t so = swz_off(row, ks8 + b_c);
                ldsm4(bf_h, sb + K8_BH + so);
                ldsm4(bf_l, sb + K8_BL + so);
                #pragma unroll
                for (int mt = 0; mt < 2; mt++)
                    #pragma unroll
                    for (int h = 0; h < 2; h++) {
                        float* ac = acc[mt][nq * 2 + h];
                        mma_bf16(ac, af_h[mt], &bf_h[h * 2]);
                        mma_bf16(ac, af_h[mt], &bf_l[h * 2]);
                        mma_bf16(ac, af_l[mt], &bf_h[h * 2]);
                    }
            }
        }
        __syncthreads();
    }

    const int g = lane >> 2;
    const int t = lane & 3;
    #pragma unroll
    for (int mt = 0; mt < 2; mt++) {
        #pragma unroll
        for (int nt = 0; nt < 6; nt++) {
            int v0 = wm * 32 + mt * 16 + g;
            int v1 = v0 + 8;
            int cg = bn + wn * 48 + nt * 8 + t * 2;
            if (cg < QAG) {
                if (v0 < NV)
                    *(float2*)(out + ((size_t)b * NV + v0) * QAG + cg) =
                        make_float2(acc[mt][nt][0], acc[mt][nt][1]);
                if (v1 < NV)
                    *(float2*)(out + ((size_t)b * NV + v1) * QAG + cg) =
                        make_float2(acc[mt][nt][2], acc[mt][nt][3]);
            }
        }
    }
}

// ---------------------------------------------------------------------------
extern "C" void kernel_launch(void* const* d_in, const int* in_sizes, int n_in,
                              void* d_out, int out_size)
{
    const float* v   = (const float*)d_in[0];
    const float* q   = (const float*)d_in[1];
    const float* a   = (const float*)d_in[2];
    const float* Wv  = (const float*)d_in[3];
    const float* bv  = (const float*)d_in[4];
    const float* Wq  = (const float*)d_in[5];
    const float* bq  = (const float*)d_in[6];
    const float* Wa  = (const float*)d_in[7];
    const float* ba  = (const float*)d_in[8];
    const float* Wvr = (const float*)d_in[9];
    const float* bvr = (const float*)d_in[10];
    const float* Wqr = (const float*)d_in[11];
    const float* bqr = (const float*)d_in[12];
    const float* War = (const float*)d_in[13];
    const float* bar = (const float*)d_in[14];
    const float* T   = (const float*)d_in[15];
    float* out       = (float*)d_out;

    __nv_bfloat16 *vhi,*vlo,*qhi,*qlo,*ahi,*alo;
    __nv_bfloat16 *Wvhi,*Wvlo,*Wqhi,*Wqlo,*Wahi,*Walo;
    __nv_bfloat16 *Wvrhi,*Wvrlo,*Wqrhi,*Wqrlo,*Warhi,*Warlo;
    __nv_bfloat16 *vthi,*vtlo,*qthi,*qtlo,*athi,*atlo,*v2hi,*v2lo;
    float *pq2,*pa2;
    cudaGetSymbolAddress((void**)&vhi, g_v_hi);   cudaGetSymbolAddress((void**)&vlo, g_v_lo);
    cudaGetSymbolAddress((void**)&qhi, g_q_hi);   cudaGetSymbolAddress((void**)&qlo, g_q_lo);
    cudaGetSymbolAddress((void**)&ahi, g_a_hi);   cudaGetSymbolAddress((void**)&alo, g_a_lo);
    cudaGetSymbolAddress((void**)&Wvhi, g_Wv_hi); cudaGetSymbolAddress((void**)&Wvlo, g_Wv_lo);
    cudaGetSymbolAddress((void**)&Wqhi, g_Wq_hi); cudaGetSymbolAddress((void**)&Wqlo, g_Wq_lo);
    cudaGetSymbolAddress((void**)&Wahi, g_Wa_hi); cudaGetSymbolAddress((void**)&Walo, g_Wa_lo);
    cudaGetSymbolAddress((void**)&Wvrhi, g_Wvr_hi); cudaGetSymbolAddress((void**)&Wvrlo, g_Wvr_lo);
    cudaGetSymbolAddress((void**)&Wqrhi, g_Wqr_hi); cudaGetSymbolAddress((void**)&Wqrlo, g_Wqr_lo);
    cudaGetSymbolAddress((void**)&Warhi, g_War_hi); cudaGetSymbolAddress((void**)&Warlo, g_War_lo);
    cudaGetSymbolAddress((void**)&vthi, g_vt_hi); cudaGetSymbolAddress((void**)&vtlo, g_vt_lo);
    cudaGetSymbolAddress((void**)&qthi, g_qt_hi); cudaGetSymbolAddress((void**)&qtlo, g_qt_lo);
    cudaGetSymbolAddress((void**)&athi, g_at_hi); cudaGetSymbolAddress((void**)&atlo, g_at_lo);
    cudaGetSymbolAddress((void**)&v2hi, g_v2_hi); cudaGetSymbolAddress((void**)&v2lo, g_v2_lo);
    cudaGetSymbolAddress((void**)&pq2, g_q2);
    cudaGetSymbolAddress((void**)&pa2, g_a2);

    cudaFuncSetAttribute(mma_gemm<0>, cudaFuncAttributeMaxDynamicSharedMemorySize, GEMM_SMEM);
    cudaFuncSetAttribute(mma_gemm<1>, cudaFuncAttributeMaxDynamicSharedMemorySize, GEMM_SMEM);
    cudaFuncSetAttribute(tq_tqa_kernel, cudaFuncAttributeMaxDynamicSharedMemorySize, 62976);
    cudaFuncSetAttribute(k8_gemm, cudaFuncAttributeMaxDynamicSharedMemorySize, K8_SMEM);

    auto split = [&](const float* x, __nv_bfloat16* h, __nv_bfloat16* l, int n) {
        int n8 = n / 8;
        split_bf16_kernel<<<(n8 + 255) / 256, 256>>>(x, h, l, n8);
    };

    // launches 1-3: inputs for the big GEMM
    split(v,   vhi,   vlo,   12800 * 2048);
    split(Wv,  Wvhi,  Wvlo,  512 * 2048);
    split(q,   qhi,   qlo,   1792  * 1024);

    // launch 4: stage-1 v projection (gets ncu-profiled)
    mma_gemm<1><<<dim3(4,100), 256, GEMM_SMEM>>>(vhi, vlo, Wvhi, Wvlo, bv,
                                                 nullptr, vthi, vtlo, 12800, 512, 2048);

    split(a,   ahi,   alo,   1280  * 1024);
    split(Wq,  Wqhi,  Wqlo,  512 * 1024);
    split(Wa,  Wahi,  Walo,  512 * 1024);
    split(Wvr, Wvrhi, Wvrlo, 512 * 512);
    split(Wqr, Wqrhi, Wqrlo, 512 * 512);
    split(War, Warhi, Warlo, 512 * 512);
    reduce_T_kernel<<<32, 256>>>(T);

    // stage 1 (q, a)
    mma_gemm<1><<<dim3(4,14), 256, GEMM_SMEM>>>(qhi, qlo, Wqhi, Wqlo, bq,
                                                nullptr, qthi, qtlo, 1792, 512, 1024);
    mma_gemm<1><<<dim3(4,10), 256, GEMM_SMEM>>>(ahi, alo, Wahi, Walo, ba,
                                                nullptr, athi, atlo, 1280, 512, 1024);

    // stage 2
    mma_gemm<1><<<dim3(4,100), 256, GEMM_SMEM>>>(vthi, vtlo, Wvrhi, Wvrlo, bvr,
                                                 nullptr, v2hi, v2lo, 12800, 512, 512);
    mma_gemm<0><<<dim3(4,14),  256, GEMM_SMEM>>>(qthi, qtlo, Wqrhi, Wqrlo, bqr,
                                                 pq2, nullptr, nullptr, 1792, 512, 512);
    mma_gemm<0><<<dim3(4,10),  256, GEMM_SMEM>>>(athi, atlo, Warhi, Warlo, bar,
                                                 pa2, nullptr, nullptr, 1280, 512, 512);

    // stage 3: Tucker core contraction -> TQA_T (bf16 hi/lo)
    tq_tqa_kernel<<<dim3(RANK, Bb), 256, 62976>>>();

    // stage 4: batched HMMA GEMM -> output
    k8_gemm<<<dim3(3, Bb), 256, K8_SMEM>>>(out);
}

// round 9
// speedup vs baseline: 1.0036x; 1.0036x over previous
#include <cuda_runtime.h>
#include <cuda_bf16.h>
#include <cstdint>

// ---------------------------------------------------------------------------
// TCNet: B=128, NV=100, NQ=14, NA=10, V_DIM=2048, Q_DIM=1024, A_DIM=1024,
//        H_DIM=512, RANK=32, HD=16, G=2
//
// einsum 'rijkg,bnvi,bnqj,bnak->bvqag' : r and n are INDEPENDENT sums.
//   Tbar[i,j,k,g] = sum_r T[r,i,j,k,g]
//   out[b,v,q,a,g] = sum_{n,i,j,k} Tbar v_ q_ a_
//
// All big GEMMs run on mma.sync bf16 (HMMA) with bf16x3 fp32 emulation:
// hi*hi + hi*lo + lo*hi.
// GEMM config: 256 threads (8 warps 4x2, warp tile 32x64), 2 CTAs/SM.
// ---------------------------------------------------------------------------

#define Bb    128
#define NV    100
#define NQ    14
#define NA    10
#define RANK  32
#define G     2
#define QAG   (NQ*NA*G)   // 280
#define CPAD  288         // padded TQA_T row count

// ---------------- scratch (static device globals, zero-initialized) --------
__device__ __align__(256) __nv_bfloat16 g_v_hi [12800*2048], g_v_lo [12800*2048];
__device__ __align__(256) __nv_bfloat16 g_q_hi [1792*1024],  g_q_lo [1792*1024];
__device__ __align__(256) __nv_bfloat16 g_a_hi [1280*1024],  g_a_lo [1280*1024];
__device__ __align__(256) __nv_bfloat16 g_Wv_hi[512*2048],   g_Wv_lo[512*2048];
__device__ __align__(256) __nv_bfloat16 g_Wq_hi[512*1024],   g_Wq_lo[512*1024];
__device__ __align__(256) __nv_bfloat16 g_Wa_hi[512*1024],   g_Wa_lo[512*1024];
__device__ __align__(256) __nv_bfloat16 g_Wvr_hi[512*512],   g_Wvr_lo[512*512];
__device__ __align__(256) __nv_bfloat16 g_Wqr_hi[512*512],   g_Wqr_lo[512*512];
__device__ __align__(256) __nv_bfloat16 g_War_hi[512*512],   g_War_lo[512*512];
__device__ __align__(256) __nv_bfloat16 g_vt_hi[12800*512],  g_vt_lo[12800*512];
__device__ __align__(256) __nv_bfloat16 g_qt_hi[1792*512],   g_qt_lo[1792*512];
__device__ __align__(256) __nv_bfloat16 g_at_hi[1280*512],   g_at_lo[1280*512];
__device__ __align__(256) __nv_bfloat16 g_v2_hi[12832*512],  g_v2_lo[12832*512];
__device__ __align__(256) float g_q2[1792*512];
__device__ __align__(256) float g_a2[1280*512];
__device__ __align__(256) __nv_bfloat16 g_tqaT_hi[128*CPAD*512];
__device__ __align__(256) __nv_bfloat16 g_tqaT_lo[128*CPAD*512];
__device__ __align__(256) float g_Tbar[8192];

// ---------------- PTX helpers ----------------
__device__ __forceinline__ uint32_t smem_u32(const void* p) {
    uint32_t a;
    asm("{ .reg .u64 t; cvta.to.shared.u64 t, %1; cvt.u32.u64 %0, t; }"
        : "=r"(a) : "l"(p));
    return a;
}
__device__ __forceinline__ void mma_bf16(float* c, const uint32_t* a,
                                         const uint32_t* b) {
    asm volatile(
        "mma.sync.aligned.m16n8k16.row.col.f32.bf16.bf16.f32 "
        "{%0,%1,%2,%3}, {%4,%5,%6,%7}, {%8,%9}, {%0,%1,%2,%3};"
        : "+f"(c[0]), "+f"(c[1]), "+f"(c[2]), "+f"(c[3])
        : "r"(a[0]), "r"(a[1]), "r"(a[2]), "r"(a[3]), "r"(b[0]), "r"(b[1]));
}
__device__ __forceinline__ void ldsm4(uint32_t* r, uint32_t addr) {
    asm volatile("ldmatrix.sync.aligned.m8n8.x4.shared.b16 {%0,%1,%2,%3}, [%4];"
                 : "=r"(r[0]), "=r"(r[1]), "=r"(r[2]), "=r"(r[3]) : "r"(addr));
}
__device__ __forceinline__ void cp16(uint32_t dst, const void* src) {
    asm volatile("cp.async.cg.shared.global [%0], [%1], 16;"
                 :: "r"(dst), "l"(src));
}
__device__ __forceinline__ void cp_commit() {
    asm volatile("cp.async.commit_group;");
}
template<int N>
__device__ __forceinline__ void cp_wait() {
    asm volatile("cp.async.wait_group %0;" :: "n"(N));
}
__device__ __forceinline__ uint32_t swz_off(int row, int c) {
    return (uint32_t)(row * 64 + ((c ^ ((row >> 1) & 3)) << 4));
}

// ---------------------------------------------------------------------------
// split fp32 -> bf16 hi/lo (8 elements per thread)
// ---------------------------------------------------------------------------
__global__ void split_bf16_kernel(const float* __restrict__ x,
                                  __nv_bfloat16* __restrict__ hi,
                                  __nv_bfloat16* __restrict__ lo, int n8)
{
    int i = blockIdx.x * 256 + threadIdx.x;
    if (i >= n8) return;
    float4 v0 = ((const float4*)x)[i * 2];
    float4 v1 = ((const float4*)x)[i * 2 + 1];
    float f[8] = {v0.x, v0.y, v0.z, v0.w, v1.x, v1.y, v1.z, v1.w};
    __nv_bfloat162 H[4], L[4];
    #pragma unroll
    for (int j = 0; j < 4; j++) {
        __nv_bfloat16 h0 = __float2bfloat16(f[j*2]);
        __nv_bfloat16 h1 = __float2bfloat16(f[j*2+1]);
        H[j] = {h0, h1};
        L[j] = {__float2bfloat16(f[j*2]   - __bfloat162float(h0)),
                __float2bfloat16(f[j*2+1] - __bfloat162float(h1))};
    }
    ((uint4*)hi)[i] = *(uint4*)H;
    ((uint4*)lo)[i] = *(uint4*)L;
}

// ---------------------------------------------------------------------------
// Tbar[x] = sum_r T[r*8192 + x]
// ---------------------------------------------------------------------------
__global__ void reduce_T_kernel(const float* __restrict__ T)
{
    int x = blockIdx.x * 256 + threadIdx.x;
    float s = 0.f;
    #pragma unroll
    for (int r = 0; r < RANK; r++) s += T[(size_t)r * 8192 + x];
    g_Tbar[x] = s;
}

// ---------------------------------------------------------------------------
// HMMA bf16x3 GEMM: C[m,n] = relu( sum_k A[m,k]*W[n,k] + bias[n] )
// BM=128, BN=128, BK=32, 256 threads (8 warps 4x2, warp tile 32x64),
// cp.async double buffer, 2 CTAs/SM.
// ---------------------------------------------------------------------------
#define STAGE_SZ 32768
#define GEMM_SMEM (2 * STAGE_SZ)
#define OFF_AH 0
#define OFF_AL 8192
#define OFF_BH 16384
#define OFF_BL 24576

template<int OUT_BF16>
__global__ __launch_bounds__(256, 2)
void mma_gemm(const __nv_bfloat16* __restrict__ Ahi,
              const __nv_bfloat16* __restrict__ Alo,
              const __nv_bfloat16* __restrict__ Bhi,
              const __nv_bfloat16* __restrict__ Blo,
              const float* __restrict__ bias,
              float* __restrict__ Cf,
              __nv_bfloat16* __restrict__ Chi,
              __nv_bfloat16* __restrict__ Clo,
              int M, int N, int K)
{
    extern __shared__ char smem[];
    const uint32_t smb = smem_u32(smem);
    const int tid  = threadIdx.x;
    const int wid  = tid >> 5;
    const int lane = tid & 31;
    const int wm   = wid & 3;          // 4 warps along M (32 rows)
    const int wn   = wid >> 2;         // 2 warps along N (64 cols)
    const int bm   = blockIdx.y * 128;
    const int bn   = blockIdx.x * 128;

    const int nchunks = K >> 5;

    auto load_stage = [&](int c) {
        const uint32_t sb = smb + (uint32_t)(c & 1) * STAGE_SZ;
        const int k0 = c << 5;
        #pragma unroll
        for (int i = 0; i < 2; i++) {
            int idx = tid + i * 256;         // 0..511
            int row = idx >> 2;
            int cc  = idx & 3;
            uint32_t so = swz_off(row, cc);
            size_t gA = (size_t)(bm + row) * K + k0 + cc * 8;
            size_t gB = (size_t)(bn + row) * K + k0 + cc * 8;
            cp16(sb + OFF_AH + so, Ahi + gA);
            cp16(sb + OFF_AL + so, Alo + gA);
            cp16(sb + OFF_BH + so, Bhi + gB);
            cp16(sb + OFF_BL + so, Blo + gB);
        }
    };

    float acc[2][8][4];
    #pragma unroll
    for (int mt = 0; mt < 2; mt++)
        #pragma unroll
        for (int nt = 0; nt < 8; nt++)
            #pragma unroll
            for (int i = 0; i < 4; i++) acc[mt][nt][i] = 0.f;

    const int a_r = (lane & 7) | (((lane >> 3) & 1) << 3);
    const int a_c = lane >> 4;
    const int b_r = (lane & 7) | ((lane >> 4) << 3);
    const int b_c = (lane >> 3) & 1;

    load_stage(0);
    cp_commit();

    for (int c = 0; c < nchunks; c++) {
        if (c + 1 < nchunks) {
            load_stage(c + 1);
            cp_commit();
            cp_wait<1>();
        } else {
            cp_wait<0>();
        }
        __syncthreads();

        const uint32_t sb = smb + (uint32_t)(c & 1) * STAGE_SZ;

        #pragma unroll
        for (int ks8 = 0; ks8 < 4; ks8 += 2) {
            uint32_t af_h[2][4], af_l[2][4];
            #pragma unroll
            for (int mt = 0; mt < 2; mt++) {
                int row = wm * 32 + mt * 16 + a_r;
                uint32_t so = swz_off(row, ks8 + a_c);
                ldsm4(af_h[mt], sb + OFF_AH + so);
                ldsm4(af_l[mt], sb + OFF_AL + so);
            }
            // per-nq B fragments (keeps register pressure low)
            #pragma unroll
            for (int nq = 0; nq < 4; nq++) {
                uint32_t bf_h[4], bf_l[4];
                int row = wn * 64 + nq * 16 + b_r;
                uint32_t so = swz_off(row, ks8 + b_c);
                ldsm4(bf_h, sb + OFF_BH + so);
                ldsm4(bf_l, sb + OFF_BL + so);
                #pragma unroll
                for (int mt = 0; mt < 2; mt++)
                    #pragma unroll
                    for (int h = 0; h < 2; h++) {
                        float* ac = acc[mt][nq * 2 + h];
                        mma_bf16(ac, af_h[mt], &bf_h[h * 2]);
                        mma_bf16(ac, af_h[mt], &bf_l[h * 2]);
                        mma_bf16(ac, af_l[mt], &bf_h[h * 2]);
                    }
            }
        }
        __syncthreads();
    }

    // epilogue: bias + relu
    const int g = lane >> 2;
    const int t = lane & 3;
    #pragma unroll
    for (int mt = 0; mt < 2; mt++) {
        #pragma unroll
        for (int nt = 0; nt < 8; nt++) {
            int row0 = bm + wm * 32 + mt * 16 + g;
            int row1 = row0 + 8;
            int col  = bn + wn * 64 + nt * 8 + t * 2;
            float bs0 = __ldg(bias + col), bs1 = __ldg(bias + col + 1);
            float v00 = fmaxf(acc[mt][nt][0] + bs0, 0.f);
            float v01 = fmaxf(acc[mt][nt][1] + bs1, 0.f);
            float v10 = fmaxf(acc[mt][nt][2] + bs0, 0.f);
            float v11 = fmaxf(acc[mt][nt][3] + bs1, 0.f);
            if (OUT_BF16) {
                __nv_bfloat16 h00 = __float2bfloat16(v00);
                __nv_bfloat16 h01 = __float2bfloat16(v01);
                __nv_bfloat16 h10 = __float2bfloat16(v10);
                __nv_bfloat16 h11 = __float2bfloat16(v11);
                __nv_bfloat162 H0 = {h00, h01}, H1 = {h10, h11};
                __nv_bfloat162 L0 = {
                    __float2bfloat16(v00 - __bfloat162float(h00)),
                    __float2bfloat16(v01 - __bfloat162float(h01))};
                __nv_bfloat162 L1 = {
                    __float2bfloat16(v10 - __bfloat162float(h10)),
                    __float2bfloat16(v11 - __bfloat162float(h11))};
                *(__nv_bfloat162*)(Chi + (size_t)row0 * N + col) = H0;
                *(__nv_bfloat162*)(Clo + (size_t)row0 * N + col) = L0;
                *(__nv_bfloat162*)(Chi + (size_t)row1 * N + col) = H1;
                *(__nv_bfloat162*)(Clo + (size_t)row1 * N + col) = L1;
            } else {
                *(float2*)(Cf + (size_t)row0 * N + col) = make_float2(v00, v01);
                *(float2*)(Cf + (size_t)row1 * N + col) = make_float2(v10, v11);
            }
        }
    }
}

// ---------------------------------------------------------------------------
// K7: per (b,n):  Tq = Tbar x_j q_,  Tqa = Tq x_k a_
// Writes TQA transposed as bf16 hi/lo: g_tqaT[b][c][n*16+ii], c=(q*10+a)*2+g
// ---------------------------------------------------------------------------
__global__ __launch_bounds__(256)
void tq_tqa_kernel()
{
    extern __shared__ float sm[];
    float* sT  = sm;               // 8192 (reused as sOut after step A)
    float* sQ  = sm + 8192;        // 224
    float* sA  = sm + 8416;        // 160
    float* sTq = sm + 8576;        // 7168

    const int n   = blockIdx.x;
    const int b   = blockIdx.y;
    const int tid = threadIdx.x;

    const float4* Tp = (const float4*)g_Tbar;
    for (int i = tid; i < 2048; i += 256) ((float4*)sT)[i] = Tp[i];

    if (tid < 56) {
        int q  = tid >> 2;
        int j4 = (tid & 3) << 2;
        *(float4*)&sQ[q * 16 + j4] =
            *(const float4*)(g_q2 + (size_t)(b * NQ + q) * 512 + n * 16 + j4);
    }
    if (tid >= 64 && tid < 104) {
        int t  = tid - 64;
        int a  = t >> 2;
        int k4 = (t & 3) << 2;
        *(float4*)&sA[a * 16 + k4] =
            *(const float4*)(g_a2 + (size_t)(b * NA + a) * 512 + n * 16 + k4);
    }
    __syncthreads();

    // step A: Tq[q,i,k,g]
    {
        const int i_ = tid >> 4;
        const int k_ = tid & 15;
        float accx[14], accy[14];
        #pragma unroll
        for (int q = 0; q < 14; q++) { accx[q] = 0.f; accy[q] = 0.f; }
        #pragma unroll
        for (int j = 0; j < 16; j++) {
            float2 t2 = *(const float2*)&sT[(((i_ * 16 + j) * 16) + k_) * 2];
            #pragma unroll
            for (int q = 0; q < 14; q++) {
                float qv = sQ[q * 16 + j];
                accx[q] = fmaf(t2.x, qv, accx[q]);
                accy[q] = fmaf(t2.y, qv, accy[q]);
            }
        }
        #pragma unroll
        for (int q = 0; q < 14; q++)
            *(float2*)&sTq[((q * 16 + i_) * 16 + k_) * 2] =
                make_float2(accx[q], accy[q]);
    }
    __syncthreads();

    // step B: contract with a_, stash transposed in sOut[ii][c]
    float* sOut = sT;   // [16][284]
    for (int t = tid; t < 2240; t += 256) {
        int ii  = t / 140;
        int rem = t - ii * 140;
        int q   = rem / 10;
        int a   = rem - q * 10;
        float sx = 0.f, sy = 0.f;
        #pragma unroll
        for (int k = 0; k < 16; k++) {
            float2 tq = *(const float2*)&sTq[((q * 16 + ii) * 16 + k) * 2];
            float  av = sA[a * 16 + k];
            sx = fmaf(tq.x, av, sx);
            sy = fmaf(tq.y, av, sy);
        }
        sOut[ii * 284 + rem * 2]     = sx;
        sOut[ii * 284 + rem * 2 + 1] = sy;
    }
    __syncthreads();

    for (int idx = tid; idx < 560; idx += 256) {
        int c    = idx >> 1;
        int half = idx & 1;
        __nv_bfloat162 H[4], L[4];
        #pragma unroll
        for (int j = 0; j < 4; j++) {
            float v0 = sOut[(half * 8 + j * 2)     * 284 + c];
            float v1 = sOut[(half * 8 + j * 2 + 1) * 284 + c];
            __nv_bfloat16 h0 = __float2bfloat16(v0);
            __nv_bfloat16 h1 = __float2bfloat16(v1);
            H[j] = {h0, h1};
            L[j] = {__float2bfloat16(v0 - __bfloat162float(h0)),
                    __float2bfloat16(v1 - __bfloat162float(h1))};
        }
        size_t off = ((size_t)b * CPAD + c) * 512 + n * 16 + half * 8;
        *(uint4*)(g_tqaT_hi + off) = *(uint4*)H;
        *(uint4*)(g_tqaT_lo + off) = *(uint4*)L;
    }
}

// ---------------------------------------------------------------------------
// K8 (HMMA): out[b][v][c] = sum_k V2[b*100+v][k] * TQA_T[b][c][k]
// BM=128 (100 valid), BN=96, BK=32, 256 threads (8 warps 4x2, warp 32x48).
// ---------------------------------------------------------------------------
#define K8_STAGE 28672
#define K8_SMEM  (2 * K8_STAGE)
#define K8_BH    16384
#define K8_BL    22528

__global__ __launch_bounds__(256, 2)
void k8_gemm(float* __restrict__ out)
{
    extern __shared__ char smem[];
    const uint32_t smb = smem_u32(smem);
    const int tid  = threadIdx.x;
    const int wid  = tid >> 5;
    const int lane = tid & 31;
    const int wm   = wid & 3;
    const int wn   = wid >> 2;
    const int bn   = blockIdx.x * 96;
    const int b    = blockIdx.y;

    const __nv_bfloat16* Ahi = g_v2_hi + (size_t)b * 100 * 512;
    const __nv_bfloat16* Alo = g_v2_lo + (size_t)b * 100 * 512;
    const __nv_bfloat16* Bhi = g_tqaT_hi + ((size_t)b * CPAD + bn) * 512;
    const __nv_bfloat16* Blo = g_tqaT_lo + ((size_t)b * CPAD + bn) * 512;

    auto load_stage = [&](int c) {
        const uint32_t sb = smb + (uint32_t)(c & 1) * K8_STAGE;
        const int k0 = c << 5;
        #pragma unroll
        for (int i = 0; i < 2; i++) {
            int idx = tid + i * 256;
            int row = idx >> 2, cc = idx & 3;
            uint32_t so = swz_off(row, cc);
            size_t g = (size_t)row * 512 + k0 + cc * 8;
            cp16(sb + OFF_AH + so, Ahi + g);
            cp16(sb + OFF_AL + so, Alo + g);
        }
        {
            int idx = tid;
            int row = idx >> 2, cc = idx & 3;
            uint32_t so = swz_off(row, cc);
            size_t g = (size_t)row * 512 + k0 + cc * 8;
            cp16(sb + K8_BH + so, Bhi + g);
            cp16(sb + K8_BL + so, Blo + g);
        }
        if (tid < 128) {
            int idx = tid + 256;
            int row = idx >> 2, cc = idx & 3;
            uint32_t so = swz_off(row, cc);
            size_t g = (size_t)row * 512 + k0 + cc * 8;
            cp16(sb + K8_BH + so, Bhi + g);
            cp16(sb + K8_BL + so, Blo + g);
        }
    };

    float acc[2][6][4];
    #pragma unroll
    for (int mt = 0; mt < 2; mt++)
        #pragma unroll
        for (int nt = 0; nt < 6; nt++)
            #pragma unroll
            for (int i = 0; i < 4; i++) acc[mt][nt][i] = 0.f;

    const int a_r = (lane & 7) | (((lane >> 3) & 1) << 3);
    const int a_c = lane >> 4;
    const int b_r = (lane & 7) | ((lane >> 4) << 3);
    const int b_c = (lane >> 3) & 1;

    load_stage(0);
    cp_commit();

    for (int c = 0; c < 16; c++) {
        if (c + 1 < 16) {
            load_stage(c + 1);
            cp_commit();
            cp_wait<1>();
        } else {
            cp_wait<0>();
        }
        __syncthreads();

        const uint32_t sb = smb + (uint32_t)(c & 1) * K8_STAGE;

        #pragma unroll
        for (int ks8 = 0; ks8 < 4; ks8 += 2) {
            uint32_t af_h[2][4], af_l[2][4];
            #pragma unroll
            for (int mt = 0; mt < 2; mt++) {
                int row = wm * 32 + mt * 16 + a_r;
                uint32_t so = swz_off(row, ks8 + a_c);
                ldsm4(af_h[mt], sb + OFF_AH + so);
                ldsm4(af_l[mt], sb + OFF_AL + so);
            }
            #pragma unroll
            for (int nq = 0; nq < 3; nq++) {
                uint32_t bf_h[4], bf_l[4];
                int row = wn * 48 + nq * 16 + b_r;
                uint32_t so = swz_off(row, ks8 + b_c);
                ldsm4(bf_h, sb + K8_BH + so);
                ldsm4(bf_l, sb + K8_BL + so);
                #pragma unroll
                for (int mt = 0; mt < 2; mt++)
                    #pragma unroll
                    for (int h = 0; h < 2; h++) {
                        float* ac = acc[mt][nq * 2 + h];
                        mma_bf16(ac, af_h[mt], &bf_h[h * 2]);
                        mma_bf16(ac, af_h[mt], &bf_l[h * 2]);
                        mma_bf16(ac, af_l[mt], &bf_h[h * 2]);
                    }
            }
        }
        __syncthreads();
    }

    const int g = lane >> 2;
    const int t = lane & 3;
    #pragma unroll
    for (int mt = 0; mt < 2; mt++) {
        #pragma unroll
        for (int nt = 0; nt < 6; nt++) {
            int v0 = wm * 32 + mt * 16 + g;
            int v1 = v0 + 8;
            int cg = bn + wn * 48 + nt * 8 + t * 2;
            if (cg < QAG) {
                if (v0 < NV)
                    *(float2*)(out + ((size_t)b * NV + v0) * QAG + cg) =
                        make_float2(acc[mt][nt][0], acc[mt][nt][1]);
                if (v1 < NV)
                    *(float2*)(out + ((size_t)b * NV + v1) * QAG + cg) =
                        make_float2(acc[mt][nt][2], acc[mt][nt][3]);
            }
        }
    }
}

// ---------------------------------------------------------------------------
extern "C" void kernel_launch(void* const* d_in, const int* in_sizes, int n_in,
                              void* d_out, int out_size)
{
    const float* v   = (const float*)d_in[0];
    const float* q   = (const float*)d_in[1];
    const float* a   = (const float*)d_in[2];
    const float* Wv  = (const float*)d_in[3];
    const float* bv  = (const float*)d_in[4];
    const float* Wq  = (const float*)d_in[5];
    const float* bq  = (const float*)d_in[6];
    const float* Wa  = (const float*)d_in[7];
    const float* ba  = (const float*)d_in[8];
    const float* Wvr = (const float*)d_in[9];
    const float* bvr = (const float*)d_in[10];
    const float* Wqr = (const float*)d_in[11];
    const float* bqr = (const float*)d_in[12];
    const float* War = (const float*)d_in[13];
    const float* bar = (const float*)d_in[14];
    const float* T   = (const float*)d_in[15];
    float* out       = (float*)d_out;

    __nv_bfloat16 *vhi,*vlo,*qhi,*qlo,*ahi,*alo;
    __nv_bfloat16 *Wvhi,*Wvlo,*Wqhi,*Wqlo,*Wahi,*Walo;
    __nv_bfloat16 *Wvrhi,*Wvrlo,*Wqrhi,*Wqrlo,*Warhi,*Warlo;
    __nv_bfloat16 *vthi,*vtlo,*qthi,*qtlo,*athi,*atlo,*v2hi,*v2lo;
    float *pq2,*pa2;
    cudaGetSymbolAddress((void**)&vhi, g_v_hi);   cudaGetSymbolAddress((void**)&vlo, g_v_lo);
    cudaGetSymbolAddress((void**)&qhi, g_q_hi);   cudaGetSymbolAddress((void**)&qlo, g_q_lo);
    cudaGetSymbolAddress((void**)&ahi, g_a_hi);   cudaGetSymbolAddress((void**)&alo, g_a_lo);
    cudaGetSymbolAddress((void**)&Wvhi, g_Wv_hi); cudaGetSymbolAddress((void**)&Wvlo, g_Wv_lo);
    cudaGetSymbolAddress((void**)&Wqhi, g_Wq_hi); cudaGetSymbolAddress((void**)&Wqlo, g_Wq_lo);
    cudaGetSymbolAddress((void**)&Wahi, g_Wa_hi); cudaGetSymbolAddress((void**)&Walo, g_Wa_lo);
    cudaGetSymbolAddress((void**)&Wvrhi, g_Wvr_hi); cudaGetSymbolAddress((void**)&Wvrlo, g_Wvr_lo);
    cudaGetSymbolAddress((void**)&Wqrhi, g_Wqr_hi); cudaGetSymbolAddress((void**)&Wqrlo, g_Wqr_lo);
    cudaGetSymbolAddress((void**)&Warhi, g_War_hi); cudaGetSymbolAddress((void**)&Warlo, g_War_lo);
    cudaGetSymbolAddress((void**)&vthi, g_vt_hi); cudaGetSymbolAddress((void**)&vtlo, g_vt_lo);
    cudaGetSymbolAddress((void**)&qthi, g_qt_hi); cudaGetSymbolAddress((void**)&qtlo, g_qt_lo);
    cudaGetSymbolAddress((void**)&athi, g_at_hi); cudaGetSymbolAddress((void**)&atlo, g_at_lo);
    cudaGetSymbolAddress((void**)&v2hi, g_v2_hi); cudaGetSymbolAddress((void**)&v2lo, g_v2_lo);
    cudaGetSymbolAddress((void**)&pq2, g_q2);
    cudaGetSymbolAddress((void**)&pa2, g_a2);

    cudaFuncSetAttribute(mma_gemm<0>, cudaFuncAttributeMaxDynamicSharedMemorySize, GEMM_SMEM);
    cudaFuncSetAttribute(mma_gemm<1>, cudaFuncAttributeMaxDynamicSharedMemorySize, GEMM_SMEM);
    cudaFuncSetAttribute(tq_tqa_kernel, cudaFuncAttributeMaxDynamicSharedMemorySize, 62976);
    cudaFuncSetAttribute(k8_gemm, cudaFuncAttributeMaxDynamicSharedMemorySize, K8_SMEM);

    auto split = [&](const float* x, __nv_bfloat16* h, __nv_bfloat16* l, int n) {
        int n8 = n / 8;
        split_bf16_kernel<<<(n8 + 255) / 256, 256>>>(x, h, l, n8);
    };

    // launches 1-3: inputs for the big GEMM
    split(v,   vhi,   vlo,   12800 * 2048);
    split(Wv,  Wvhi,  Wvlo,  512 * 2048);
    split(q,   qhi,   qlo,   1792  * 1024);

    // launch 4: stage-1 v projection (gets ncu-profiled)
    mma_gemm<1><<<dim3(4,100), 256, GEMM_SMEM>>>(vhi, vlo, Wvhi, Wvlo, bv,
                                                 nullptr, vthi, vtlo, 12800, 512, 2048);

    split(a,   ahi,   alo,   1280  * 1024);
    split(Wq,  Wqhi,  Wqlo,  512 * 1024);
    split(Wa,  Wahi,  Walo,  512 * 1024);
    split(Wvr, Wvrhi, Wvrlo, 512 * 512);
    split(Wqr, Wqrhi, Wqrlo, 512 * 512);
    split(War, Warhi, Warlo, 512 * 512);
    reduce_T_kernel<<<32, 256>>>(T);

    // stage 1 (q, a)
    mma_gemm<1><<<dim3(4,14), 256, GEMM_SMEM>>>(qhi, qlo, Wqhi, Wqlo, bq,
                                                nullptr, qthi, qtlo, 1792, 512, 1024);
    mma_gemm<1><<<dim3(4,10), 256, GEMM_SMEM>>>(ahi, alo, Wahi, Walo, ba,
                                                nullptr, athi, atlo, 1280, 512, 1024);

    // stage 2
    mma_gemm<1><<<dim3(4,100), 256, GEMM_SMEM>>>(vthi, vtlo, Wvrhi, Wvrlo, bvr,
                                                 nullptr, v2hi, v2lo, 12800, 512, 512);
    mma_gemm<0><<<dim3(4,14),  256, GEMM_SMEM>>>(qthi, qtlo, Wqrhi, Wqrlo, bqr,
                                                 pq2, nullptr, nullptr, 1792, 512, 512);
    mma_gemm<0><<<dim3(4,10),  256, GEMM_SMEM>>>(athi, atlo, Warhi, Warlo, bar,
                                                 pa2, nullptr, nullptr, 1280, 512, 512);

    // stage 3: Tucker core contraction -> TQA_T (bf16 hi/lo)
    tq_tqa_kernel<<<dim3(RANK, Bb), 256, 62976>>>();

    // stage 4: batched HMMA GEMM -> output
    k8_gemm<<<dim3(3, Bb), 256, K8_SMEM>>>(out);
}

// round 10
// speedup vs baseline: 1.0073x; 1.0037x over previous
#include <cuda_runtime.h>
#include <cuda_bf16.h>
#include <cstdint>

// ---------------------------------------------------------------------------
// TCNet: B=128, NV=100, NQ=14, NA=10, V_DIM=2048, Q_DIM=1024, A_DIM=1024,
//        H_DIM=512, RANK=32, HD=16, G=2
//
// einsum 'rijkg,bnvi,bnqj,bnak->bvqag' : r and n are INDEPENDENT sums.
//   Tbar[i,j,k,g] = sum_r T[r,i,j,k,g]
//   out[b,v,q,a,g] = sum_{n,i,j,k} Tbar v_ q_ a_
//
// All big GEMMs run on mma.sync bf16 (HMMA) with bf16x3 fp32 emulation:
// hi*hi + hi*lo + lo*hi.
// GEMM config: 256 threads (8 warps 4x2, warp tile 32x64), 2 CTAs/SM,
// 3-stage cp.async pipeline, ONE __syncthreads per K-chunk.
// ---------------------------------------------------------------------------

#define Bb    128
#define NV    100
#define NQ    14
#define NA    10
#define RANK  32
#define G     2
#define QAG   (NQ*NA*G)   // 280
#define CPAD  288         // padded TQA_T row count

// ---------------- scratch (static device globals, zero-initialized) --------
__device__ __align__(256) __nv_bfloat16 g_v_hi [12800*2048], g_v_lo [12800*2048];
__device__ __align__(256) __nv_bfloat16 g_q_hi [1792*1024],  g_q_lo [1792*1024];
__device__ __align__(256) __nv_bfloat16 g_a_hi [1280*1024],  g_a_lo [1280*1024];
__device__ __align__(256) __nv_bfloat16 g_Wv_hi[512*2048],   g_Wv_lo[512*2048];
__device__ __align__(256) __nv_bfloat16 g_Wq_hi[512*1024],   g_Wq_lo[512*1024];
__device__ __align__(256) __nv_bfloat16 g_Wa_hi[512*1024],   g_Wa_lo[512*1024];
__device__ __align__(256) __nv_bfloat16 g_Wvr_hi[512*512],   g_Wvr_lo[512*512];
__device__ __align__(256) __nv_bfloat16 g_Wqr_hi[512*512],   g_Wqr_lo[512*512];
__device__ __align__(256) __nv_bfloat16 g_War_hi[512*512],   g_War_lo[512*512];
__device__ __align__(256) __nv_bfloat16 g_vt_hi[12800*512],  g_vt_lo[12800*512];
__device__ __align__(256) __nv_bfloat16 g_qt_hi[1792*512],   g_qt_lo[1792*512];
__device__ __align__(256) __nv_bfloat16 g_at_hi[1280*512],   g_at_lo[1280*512];
__device__ __align__(256) __nv_bfloat16 g_v2_hi[12832*512],  g_v2_lo[12832*512];
__device__ __align__(256) float g_q2[1792*512];
__device__ __align__(256) float g_a2[1280*512];
__device__ __align__(256) __nv_bfloat16 g_tqaT_hi[128*CPAD*512];
__device__ __align__(256) __nv_bfloat16 g_tqaT_lo[128*CPAD*512];
__device__ __align__(256) float g_Tbar[8192];

// ---------------- PTX helpers ----------------
__device__ __forceinline__ uint32_t smem_u32(const void* p) {
    uint32_t a;
    asm("{ .reg .u64 t; cvta.to.shared.u64 t, %1; cvt.u32.u64 %0, t; }"
        : "=r"(a) : "l"(p));
    return a;
}
__device__ __forceinline__ void mma_bf16(float* c, const uint32_t* a,
                                         const uint32_t* b) {
    asm volatile(
        "mma.sync.aligned.m16n8k16.row.col.f32.bf16.bf16.f32 "
        "{%0,%1,%2,%3}, {%4,%5,%6,%7}, {%8,%9}, {%0,%1,%2,%3};"
        : "+f"(c[0]), "+f"(c[1]), "+f"(c[2]), "+f"(c[3])
        : "r"(a[0]), "r"(a[1]), "r"(a[2]), "r"(a[3]), "r"(b[0]), "r"(b[1]));
}
__device__ __forceinline__ void ldsm4(uint32_t* r, uint32_t addr) {
    asm volatile("ldmatrix.sync.aligned.m8n8.x4.shared.b16 {%0,%1,%2,%3}, [%4];"
                 : "=r"(r[0]), "=r"(r[1]), "=r"(r[2]), "=r"(r[3]) : "r"(addr));
}
__device__ __forceinline__ void cp16(uint32_t dst, const void* src) {
    asm volatile("cp.async.cg.shared.global [%0], [%1], 16;"
                 :: "r"(dst), "l"(src));
}
__device__ __forceinline__ void cp_commit() {
    asm volatile("cp.async.commit_group;");
}
template<int N>
__device__ __forceinline__ void cp_wait() {
    asm volatile("cp.async.wait_group %0;" :: "n"(N));
}
__device__ __forceinline__ uint32_t swz_off(int row, int c) {
    return (uint32_t)(row * 64 + ((c ^ ((row >> 1) & 3)) << 4));
}

// ---------------------------------------------------------------------------
// split fp32 -> bf16 hi/lo (8 elements per thread)
// ---------------------------------------------------------------------------
__global__ void split_bf16_kernel(const float* __restrict__ x,
                                  __nv_bfloat16* __restrict__ hi,
                                  __nv_bfloat16* __restrict__ lo, int n8)
{
    int i = blockIdx.x * 256 + threadIdx.x;
    if (i >= n8) return;
    float4 v0 = ((const float4*)x)[i * 2];
    float4 v1 = ((const float4*)x)[i * 2 + 1];
    float f[8] = {v0.x, v0.y, v0.z, v0.w, v1.x, v1.y, v1.z, v1.w};
    __nv_bfloat162 H[4], L[4];
    #pragma unroll
    for (int j = 0; j < 4; j++) {
        __nv_bfloat16 h0 = __float2bfloat16(f[j*2]);
        __nv_bfloat16 h1 = __float2bfloat16(f[j*2+1]);
        H[j] = {h0, h1};
        L[j] = {__float2bfloat16(f[j*2]   - __bfloat162float(h0)),
                __float2bfloat16(f[j*2+1] - __bfloat162float(h1))};
    }
    ((uint4*)hi)[i] = *(uint4*)H;
    ((uint4*)lo)[i] = *(uint4*)L;
}

// ---------------------------------------------------------------------------
// Tbar[x] = sum_r T[r*8192 + x]
// ---------------------------------------------------------------------------
__global__ void reduce_T_kernel(const float* __restrict__ T)
{
    int x = blockIdx.x * 256 + threadIdx.x;
    float s = 0.f;
    #pragma unroll
    for (int r = 0; r < RANK; r++) s += T[(size_t)r * 8192 + x];
    g_Tbar[x] = s;
}

// ---------------------------------------------------------------------------
// HMMA bf16x3 GEMM: C[m,n] = relu( sum_k A[m,k]*W[n,k] + bias[n] )
// BM=128, BN=128, BK=32, 256 threads (8 warps 4x2, warp tile 32x64),
// 3-stage cp.async pipeline, one __syncthreads per chunk, 2 CTAs/SM.
// ---------------------------------------------------------------------------
#define STAGE_SZ 32768
#define GEMM_SMEM (3 * STAGE_SZ)       // 98304
#define OFF_AH 0
#define OFF_AL 8192
#define OFF_BH 16384
#define OFF_BL 24576

template<int OUT_BF16>
__global__ __launch_bounds__(256, 2)
void mma_gemm(const __nv_bfloat16* __restrict__ Ahi,
              const __nv_bfloat16* __restrict__ Alo,
              const __nv_bfloat16* __restrict__ Bhi,
              const __nv_bfloat16* __restrict__ Blo,
              const float* __restrict__ bias,
              float* __restrict__ Cf,
              __nv_bfloat16* __restrict__ Chi,
              __nv_bfloat16* __restrict__ Clo,
              int M, int N, int K)
{
    extern __shared__ char smem[];
    const uint32_t smb = smem_u32(smem);
    const int tid  = threadIdx.x;
    const int wid  = tid >> 5;
    const int lane = tid & 31;
    const int wm   = wid & 3;
    const int wn   = wid >> 2;
    const int bm   = blockIdx.y * 128;
    const int bn   = blockIdx.x * 128;

    const int nchunks = K >> 5;

    auto load_stage = [&](int c) {
        const uint32_t sb = smb + (uint32_t)(c % 3) * STAGE_SZ;
        const int k0 = c << 5;
        #pragma unroll
        for (int i = 0; i < 2; i++) {
            int idx = tid + i * 256;
            int row = idx >> 2;
            int cc  = idx & 3;
            uint32_t so = swz_off(row, cc);
            size_t gA = (size_t)(bm + row) * K + k0 + cc * 8;
            size_t gB = (size_t)(bn + row) * K + k0 + cc * 8;
            cp16(sb + OFF_AH + so, Ahi + gA);
            cp16(sb + OFF_AL + so, Alo + gA);
            cp16(sb + OFF_BH + so, Bhi + gB);
            cp16(sb + OFF_BL + so, Blo + gB);
        }
    };

    float acc[2][8][4];
    #pragma unroll
    for (int mt = 0; mt < 2; mt++)
        #pragma unroll
        for (int nt = 0; nt < 8; nt++)
            #pragma unroll
            for (int i = 0; i < 4; i++) acc[mt][nt][i] = 0.f;

    const int a_r = (lane & 7) | (((lane >> 3) & 1) << 3);
    const int a_c = lane >> 4;
    const int b_r = (lane & 7) | ((lane >> 4) << 3);
    const int b_c = (lane >> 3) & 1;

    load_stage(0);
    cp_commit();
    load_stage(1);
    cp_commit();

    for (int c = 0; c < nchunks; c++) {
        cp_wait<1>();           // stage c resident (c+1 may be in flight)
        __syncthreads();        // all warps: stage c visible; compute c-1 done

        if (c + 2 < nchunks) {  // prefetch into (c+2)%3 == (c-1)%3 buffer
            load_stage(c + 2);
            cp_commit();
        } else {
            cp_commit();        // keep group count in lockstep
        }

        const uint32_t sb = smb + (uint32_t)(c % 3) * STAGE_SZ;

        #pragma unroll
        for (int ks8 = 0; ks8 < 4; ks8 += 2) {
            uint32_t af_h[2][4], af_l[2][4];
            #pragma unroll
            for (int mt = 0; mt < 2; mt++) {
                int row = wm * 32 + mt * 16 + a_r;
                uint32_t so = swz_off(row, ks8 + a_c);
                ldsm4(af_h[mt], sb + OFF_AH + so);
                ldsm4(af_l[mt], sb + OFF_AL + so);
            }
            #pragma unroll
            for (int nq = 0; nq < 4; nq++) {
                uint32_t bf_h[4], bf_l[4];
                int row = wn * 64 + nq * 16 + b_r;
                uint32_t so = swz_off(row, ks8 + b_c);
                ldsm4(bf_h, sb + OFF_BH + so);
                ldsm4(bf_l, sb + OFF_BL + so);
                #pragma unroll
                for (int mt = 0; mt < 2; mt++)
                    #pragma unroll
                    for (int h = 0; h < 2; h++) {
                        float* ac = acc[mt][nq * 2 + h];
                        mma_bf16(ac, af_h[mt], &bf_h[h * 2]);
                        mma_bf16(ac, af_h[mt], &bf_l[h * 2]);
                        mma_bf16(ac, af_l[mt], &bf_h[h * 2]);
                    }
            }
        }
    }

    // epilogue: bias + relu
    const int g = lane >> 2;
    const int t = lane & 3;
    #pragma unroll
    for (int mt = 0; mt < 2; mt++) {
        #pragma unroll
        for (int nt = 0; nt < 8; nt++) {
            int row0 = bm + wm * 32 + mt * 16 + g;
            int row1 = row0 + 8;
            int col  = bn + wn * 64 + nt * 8 + t * 2;
            float bs0 = __ldg(bias + col), bs1 = __ldg(bias + col + 1);
            float v00 = fmaxf(acc[mt][nt][0] + bs0, 0.f);
            float v01 = fmaxf(acc[mt][nt][1] + bs1, 0.f);
            float v10 = fmaxf(acc[mt][nt][2] + bs0, 0.f);
            float v11 = fmaxf(acc[mt][nt][3] + bs1, 0.f);
            if (OUT_BF16) {
                __nv_bfloat16 h00 = __float2bfloat16(v00);
                __nv_bfloat16 h01 = __float2bfloat16(v01);
                __nv_bfloat16 h10 = __float2bfloat16(v10);
                __nv_bfloat16 h11 = __float2bfloat16(v11);
                __nv_bfloat162 H0 = {h00, h01}, H1 = {h10, h11};
                __nv_bfloat162 L0 = {
                    __float2bfloat16(v00 - __bfloat162float(h00)),
                    __float2bfloat16(v01 - __bfloat162float(h01))};
                __nv_bfloat162 L1 = {
                    __float2bfloat16(v10 - __bfloat162float(h10)),
                    __float2bfloat16(v11 - __bfloat162float(h11))};
                *(__nv_bfloat162*)(Chi + (size_t)row0 * N + col) = H0;
                *(__nv_bfloat162*)(Clo + (size_t)row0 * N + col) = L0;
                *(__nv_bfloat162*)(Chi + (size_t)row1 * N + col) = H1;
                *(__nv_bfloat162*)(Clo + (size_t)row1 * N + col) = L1;
            } else {
                *(float2*)(Cf + (size_t)row0 * N + col) = make_float2(v00, v01);
                *(float2*)(Cf + (size_t)row1 * N + col) = make_float2(v10, v11);
            }
        }
    }
}

// ---------------------------------------------------------------------------
// K7: per (b,n):  Tq = Tbar x_j q_,  Tqa = Tq x_k a_
// Writes TQA transposed as bf16 hi/lo: g_tqaT[b][c][n*16+ii], c=(q*10+a)*2+g
// ---------------------------------------------------------------------------
__global__ __launch_bounds__(256)
void tq_tqa_kernel()
{
    extern __shared__ float sm[];
    float* sT  = sm;               // 8192 (reused as sOut after step A)
    float* sQ  = sm + 8192;        // 224
    float* sA  = sm + 8416;        // 160
    float* sTq = sm + 8576;        // 7168

    const int n   = blockIdx.x;
    const int b   = blockIdx.y;
    const int tid = threadIdx.x;

    const float4* Tp = (const float4*)g_Tbar;
    for (int i = tid; i < 2048; i += 256) ((float4*)sT)[i] = Tp[i];

    if (tid < 56) {
        int q  = tid >> 2;
        int j4 = (tid & 3) << 2;
        *(float4*)&sQ[q * 16 + j4] =
            *(const float4*)(g_q2 + (size_t)(b * NQ + q) * 512 + n * 16 + j4);
    }
    if (tid >= 64 && tid < 104) {
        int t  = tid - 64;
        int a  = t >> 2;
        int k4 = (t & 3) << 2;
        *(float4*)&sA[a * 16 + k4] =
            *(const float4*)(g_a2 + (size_t)(b * NA + a) * 512 + n * 16 + k4);
    }
    __syncthreads();

    // step A: Tq[q,i,k,g]
    {
        const int i_ = tid >> 4;
        const int k_ = tid & 15;
        float accx[14], accy[14];
        #pragma unroll
        for (int q = 0; q < 14; q++) { accx[q] = 0.f; accy[q] = 0.f; }
        #pragma unroll
        for (int j = 0; j < 16; j++) {
            float2 t2 = *(const float2*)&sT[(((i_ * 16 + j) * 16) + k_) * 2];
            #pragma unroll
            for (int q = 0; q < 14; q++) {
                float qv = sQ[q * 16 + j];
                accx[q] = fmaf(t2.x, qv, accx[q]);
                accy[q] = fmaf(t2.y, qv, accy[q]);
            }
        }
        #pragma unroll
        for (int q = 0; q < 14; q++)
            *(float2*)&sTq[((q * 16 + i_) * 16 + k_) * 2] =
                make_float2(accx[q], accy[q]);
    }
    __syncthreads();

    // step B: contract with a_, stash transposed in sOut[ii][c]
    float* sOut = sT;   // [16][284]
    for (int t = tid; t < 2240; t += 256) {
        int ii  = t / 140;
        int rem = t - ii * 140;
        int q   = rem / 10;
        int a   = rem - q * 10;
        float sx = 0.f, sy = 0.f;
        #pragma unroll
        for (int k = 0; k < 16; k++) {
            float2 tq = *(const float2*)&sTq[((q * 16 + ii) * 16 + k) * 2];
            float  av = sA[a * 16 + k];
            sx = fmaf(tq.x, av, sx);
            sy = fmaf(tq.y, av, sy);
        }
        sOut[ii * 284 + rem * 2]     = sx;
        sOut[ii * 284 + rem * 2 + 1] = sy;
    }
    __syncthreads();

    for (int idx = tid; idx < 560; idx += 256) {
        int c    = idx >> 1;
        int half = idx & 1;
        __nv_bfloat162 H[4], L[4];
        #pragma unroll
        for (int j = 0; j < 4; j++) {
            float v0 = sOut[(half * 8 + j * 2)     * 284 + c];
            float v1 = sOut[(half * 8 + j * 2 + 1) * 284 + c];
            __nv_bfloat16 h0 = __float2bfloat16(v0);
            __nv_bfloat16 h1 = __float2bfloat16(v1);
            H[j] = {h0, h1};
            L[j] = {__float2bfloat16(v0 - __bfloat162float(h0)),
                    __float2bfloat16(v1 - __bfloat162float(h1))};
        }
        size_t off = ((size_t)b * CPAD + c) * 512 + n * 16 + half * 8;
        *(uint4*)(g_tqaT_hi + off) = *(uint4*)H;
        *(uint4*)(g_tqaT_lo + off) = *(uint4*)L;
    }
}

// ---------------------------------------------------------------------------
// K8 (HMMA): out[b][v][c] = sum_k V2[b*100+v][k] * TQA_T[b][c][k]
// BM=128 (100 valid), BN=96, BK=32, 256 threads, 3-stage pipeline.
// ---------------------------------------------------------------------------
#define K8_STAGE 28672
#define K8_SMEM  (3 * K8_STAGE)        // 86016
#define K8_BH    16384
#define K8_BL    22528

__global__ __launch_bounds__(256, 2)
void k8_gemm(float* __restrict__ out)
{
    extern __shared__ char smem[];
    const uint32_t smb = smem_u32(smem);
    const int tid  = threadIdx.x;
    const int wid  = tid >> 5;
    const int lane = tid & 31;
    const int wm   = wid & 3;
    const int wn   = wid >> 2;
    const int bn   = blockIdx.x * 96;
    const int b    = blockIdx.y;

    const __nv_bfloat16* Ahi = g_v2_hi + (size_t)b * 100 * 512;
    const __nv_bfloat16* Alo = g_v2_lo + (size_t)b * 100 * 512;
    const __nv_bfloat16* Bhi = g_tqaT_hi + ((size_t)b * CPAD + bn) * 512;
    const __nv_bfloat16* Blo = g_tqaT_lo + ((size_t)b * CPAD + bn) * 512;

    auto load_stage = [&](int c) {
        const uint32_t sb = smb + (uint32_t)(c % 3) * K8_STAGE;
        const int k0 = c << 5;
        #pragma unroll
        for (int i = 0; i < 2; i++) {
            int idx = tid + i * 256;
            int row = idx >> 2, cc = idx & 3;
            uint32_t so = swz_off(row, cc);
            size_t g = (size_t)row * 512 + k0 + cc * 8;
            cp16(sb + OFF_AH + so, Ahi + g);
            cp16(sb + OFF_AL + so, Alo + g);
        }
        {
            int idx = tid;
            int row = idx >> 2, cc = idx & 3;
            uint32_t so = swz_off(row, cc);
            size_t g = (size_t)row * 512 + k0 + cc * 8;
            cp16(sb + K8_BH + so, Bhi + g);
            cp16(sb + K8_BL + so, Blo + g);
        }
        if (tid < 128) {
            int idx = tid + 256;
            int row = idx >> 2, cc = idx & 3;
            uint32_t so = swz_off(row, cc);
            size_t g = (size_t)row * 512 + k0 + cc * 8;
            cp16(sb + K8_BH + so, Bhi + g);
            cp16(sb + K8_BL + so, Blo + g);
        }
    };

    float acc[2][6][4];
    #pragma unroll
    for (int mt = 0; mt < 2; mt++)
        #pragma unroll
        for (int nt = 0; nt < 6; nt++)
            #pragma unroll
            for (int i = 0; i < 4; i++) acc[mt][nt][i] = 0.f;

    const int a_r = (lane & 7) | (((lane >> 3) & 1) << 3);
    const int a_c = lane >> 4;
    const int b_r = (lane & 7) | ((lane >> 4) << 3);
    const int b_c = (lane >> 3) & 1;

    load_stage(0);
    cp_commit();
    load_stage(1);
    cp_commit();

    for (int c = 0; c < 16; c++) {
        cp_wait<1>();
        __syncthreads();

        if (c + 2 < 16) {
            load_stage(c + 2);
            cp_commit();
        } else {
            cp_commit();
        }

        const uint32_t sb = smb + (uint32_t)(c % 3) * K8_STAGE;

        #pragma unroll
        for (int ks8 = 0; ks8 < 4; ks8 += 2) {
            uint32_t af_h[2][4], af_l[2][4];
            #pragma unroll
            for (int mt = 0; mt < 2; mt++) {
                int row = wm * 32 + mt * 16 + a_r;
                uint32_t so = swz_off(row, ks8 + a_c);
                ldsm4(af_h[mt], sb + OFF_AH + so);
                ldsm4(af_l[mt], sb + OFF_AL + so);
            }
            #pragma unroll
            for (int nq = 0; nq < 3; nq++) {
                uint32_t bf_h[4], bf_l[4];
                int row = wn * 48 + nq * 16 + b_r;
                uint32_t so = swz_off(row, ks8 + b_c);
                ldsm4(bf_h, sb + K8_BH + so);
                ldsm4(bf_l, sb + K8_BL + so);
                #pragma unroll
                for (int mt = 0; mt < 2; mt++)
                    #pragma unroll
                    for (int h = 0; h < 2; h++) {
                        float* ac = acc[mt][nq * 2 + h];
                        mma_bf16(ac, af_h[mt], &bf_h[h * 2]);
                        mma_bf16(ac, af_h[mt], &bf_l[h * 2]);
                        mma_bf16(ac, af_l[mt], &bf_h[h * 2]);
                    }
            }
        }
    }

    const int g = lane >> 2;
    const int t = lane & 3;
    #pragma unroll
    for (int mt = 0; mt < 2; mt++) {
        #pragma unroll
        for (int nt = 0; nt < 6; nt++) {
            int v0 = wm * 32 + mt * 16 + g;
            int v1 = v0 + 8;
            int cg = bn + wn * 48 + nt * 8 + t * 2;
            if (cg < QAG) {
                if (v0 < NV)
                    *(float2*)(out + ((size_t)b * NV + v0) * QAG + cg) =
                        make_float2(acc[mt][nt][0], acc[mt][nt][1]);
                if (v1 < NV)
                    *(float2*)(out + ((size_t)b * NV + v1) * QAG + cg) =
                        make_float2(acc[mt][nt][2], acc[mt][nt][3]);
            }
        }
    }
}

// ---------------------------------------------------------------------------
extern "C" void kernel_launch(void* const* d_in, const int* in_sizes, int n_in,
                              void* d_out, int out_size)
{
    const float* v   = (const float*)d_in[0];
    const float* q   = (const float*)d_in[1];
    const float* a   = (const float*)d_in[2];
    const float* Wv  = (const float*)d_in[3];
    const float* bv  = (const float*)d_in[4];
    const float* Wq  = (const float*)d_in[5];
    const float* bq  = (const float*)d_in[6];
    const float* Wa  = (const float*)d_in[7];
    const float* ba  = (const float*)d_in[8];
    const float* Wvr = (const float*)d_in[9];
    const float* bvr = (const float*)d_in[10];
    const float* Wqr = (const float*)d_in[11];
    const float* bqr = (const float*)d_in[12];
    const float* War = (const float*)d_in[13];
    const float* bar = (const float*)d_in[14];
    const float* T   = (const float*)d_in[15];
    float* out       = (float*)d_out;

    __nv_bfloat16 *vhi,*vlo,*qhi,*qlo,*ahi,*alo;
    __nv_bfloat16 *Wvhi,*Wvlo,*Wqhi,*Wqlo,*Wahi,*Walo;
    __nv_bfloat16 *Wvrhi,*Wvrlo,*Wqrhi,*Wqrlo,*Warhi,*Warlo;
    __nv_bfloat16 *vthi,*vtlo,*qthi,*qtlo,*athi,*atlo,*v2hi,*v2lo;
    float *pq2,*pa2;
    cudaGetSymbolAddress((void**)&vhi, g_v_hi);   cudaGetSymbolAddress((void**)&vlo, g_v_lo);
    cudaGetSymbolAddress((void**)&qhi, g_q_hi);   cudaGetSymbolAddress((void**)&qlo, g_q_lo);
    cudaGetSymbolAddress((void**)&ahi, g_a_hi);   cudaGetSymbolAddress((void**)&alo, g_a_lo);
    cudaGetSymbolAddress((void**)&Wvhi, g_Wv_hi); cudaGetSymbolAddress((void**)&Wvlo, g_Wv_lo);
    cudaGetSymbolAddress((void**)&Wqhi, g_Wq_hi); cudaGetSymbolAddress((void**)&Wqlo, g_Wq_lo);
    cudaGetSymbolAddress((void**)&Wahi, g_Wa_hi); cudaGetSymbolAddress((void**)&Walo, g_Wa_lo);
    cudaGetSymbolAddress((void**)&Wvrhi, g_Wvr_hi); cudaGetSymbolAddress((void**)&Wvrlo, g_Wvr_lo);
    cudaGetSymbolAddress((void**)&Wqrhi, g_Wqr_hi); cudaGetSymbolAddress((void**)&Wqrlo, g_Wqr_lo);
    cudaGetSymbolAddress((void**)&Warhi, g_War_hi); cudaGetSymbolAddress((void**)&Warlo, g_War_lo);
    cudaGetSymbolAddress((void**)&vthi, g_vt_hi); cudaGetSymbolAddress((void**)&vtlo, g_vt_lo);
    cudaGetSymbolAddress((void**)&qthi, g_qt_hi); cudaGetSymbolAddress((void**)&qtlo, g_qt_lo);
    cudaGetSymbolAddress((void**)&athi, g_at_hi); cudaGetSymbolAddress((void**)&atlo, g_at_lo);
    cudaGetSymbolAddress((void**)&v2hi, g_v2_hi); cudaGetSymbolAddress((void**)&v2lo, g_v2_lo);
    cudaGetSymbolAddress((void**)&pq2, g_q2);
    cudaGetSymbolAddress((void**)&pa2, g_a2);

    cudaFuncSetAttribute(mma_gemm<0>, cudaFuncAttributeMaxDynamicSharedMemorySize, GEMM_SMEM);
    cudaFuncSetAttribute(mma_gemm<1>, cudaFuncAttributeMaxDynamicSharedMemorySize, GEMM_SMEM);
    cudaFuncSetAttribute(tq_tqa_kernel, cudaFuncAttributeMaxDynamicSharedMemorySize, 62976);
    cudaFuncSetAttribute(k8_gemm, cudaFuncAttributeMaxDynamicSharedMemorySize, K8_SMEM);

    auto split = [&](const float* x, __nv_bfloat16* h, __nv_bfloat16* l, int n) {
        int n8 = n / 8;
        split_bf16_kernel<<<(n8 + 255) / 256, 256>>>(x, h, l, n8);
    };

    // launches 1-3: inputs for the big GEMM
    split(v,   vhi,   vlo,   12800 * 2048);
    split(Wv,  Wvhi,  Wvlo,  512 * 2048);
    split(q,   qhi,   qlo,   1792  * 1024);

    // launch 4: stage-1 v projection (gets ncu-profiled)
    mma_gemm<1><<<dim3(4,100), 256, GEMM_SMEM>>>(vhi, vlo, Wvhi, Wvlo, bv,
                                                 nullptr, vthi, vtlo, 12800, 512, 2048);

    split(a,   ahi,   alo,   1280  * 1024);
    split(Wq,  Wqhi,  Wqlo,  512 * 1024);
    split(Wa,  Wahi,  Walo,  512 * 1024);
    split(Wvr, Wvrhi, Wvrlo, 512 * 512);
    split(Wqr, Wqrhi, Wqrlo, 512 * 512);
    split(War, Warhi, Warlo, 512 * 512);
    reduce_T_kernel<<<32, 256>>>(T);

    // stage 1 (q, a)
    mma_gemm<1><<<dim3(4,14), 256, GEMM_SMEM>>>(qhi, qlo, Wqhi, Wqlo, bq,
                                                nullptr, qthi, qtlo, 1792, 512, 1024);
    mma_gemm<1><<<dim3(4,10), 256, GEMM_SMEM>>>(ahi, alo, Wahi, Walo, ba,
                                                nullptr, athi, atlo, 1280, 512, 1024);

    // stage 2
    mma_gemm<1><<<dim3(4,100), 256, GEMM_SMEM>>>(vthi, vtlo, Wvrhi, Wvrlo, bvr,
                                                 nullptr, v2hi, v2lo, 12800, 512, 512);
    mma_gemm<0><<<dim3(4,14),  256, GEMM_SMEM>>>(qthi, qtlo, Wqrhi, Wqrlo, bqr,
                                                 pq2, nullptr, nullptr, 1792, 512, 512);
    mma_gemm<0><<<dim3(4,10),  256, GEMM_SMEM>>>(athi, atlo, Warhi, Warlo, bar,
                                                 pa2, nullptr, nullptr, 1280, 512, 512);

    // stage 3: Tucker core contraction -> TQA_T (bf16 hi/lo)
    tq_tqa_kernel<<<dim3(RANK, Bb), 256, 62976>>>();

    // stage 4: batched HMMA GEMM -> output
    k8_gemm<<<dim3(3, Bb), 256, K8_SMEM>>>(out);
}

// round 11
// speedup vs baseline: 1.0470x; 1.0394x over previous
#include <cuda_runtime.h>
#include <cuda_bf16.h>
#include <cstdint>

// ---------------------------------------------------------------------------
// TCNet: B=128, NV=100, NQ=14, NA=10, V_DIM=2048, Q_DIM=1024, A_DIM=1024,
//        H_DIM=512, RANK=32, HD=16, G=2
//
// einsum 'rijkg,bnvi,bnqj,bnak->bvqag' : r and n are INDEPENDENT sums.
//   Tbar[i,j,k,g] = sum_r T[r,i,j,k,g]
//   out[b,v,q,a,g] = sum_{n,i,j,k} Tbar v_ q_ a_
//
// All big GEMMs run on mma.sync bf16 (HMMA) with bf16x3 fp32 emulation.
// GEMM config this round: BM=128, BN=64, 8 warps (warp tile 32x32),
// 3 CTAs/SM (wave-quantization fix: grid 800 -> 90% slot utilization).
// ---------------------------------------------------------------------------

#define Bb    128
#define NV    100
#define NQ    14
#define NA    10
#define RANK  32
#define G     2
#define QAG   (NQ*NA*G)   // 280
#define CPAD  288         // padded TQA_T row count

// ---------------- scratch (static device globals, zero-initialized) --------
__device__ __align__(256) __nv_bfloat16 g_v_hi [12800*2048], g_v_lo [12800*2048];
__device__ __align__(256) __nv_bfloat16 g_q_hi [1792*1024],  g_q_lo [1792*1024];
__device__ __align__(256) __nv_bfloat16 g_a_hi [1280*1024],  g_a_lo [1280*1024];
__device__ __align__(256) __nv_bfloat16 g_Wv_hi[512*2048],   g_Wv_lo[512*2048];
__device__ __align__(256) __nv_bfloat16 g_Wq_hi[512*1024],   g_Wq_lo[512*1024];
__device__ __align__(256) __nv_bfloat16 g_Wa_hi[512*1024],   g_Wa_lo[512*1024];
__device__ __align__(256) __nv_bfloat16 g_Wvr_hi[512*512],   g_Wvr_lo[512*512];
__device__ __align__(256) __nv_bfloat16 g_Wqr_hi[512*512],   g_Wqr_lo[512*512];
__device__ __align__(256) __nv_bfloat16 g_War_hi[512*512],   g_War_lo[512*512];
__device__ __align__(256) __nv_bfloat16 g_vt_hi[12800*512],  g_vt_lo[12800*512];
__device__ __align__(256) __nv_bfloat16 g_qt_hi[1792*512],   g_qt_lo[1792*512];
__device__ __align__(256) __nv_bfloat16 g_at_hi[1280*512],   g_at_lo[1280*512];
__device__ __align__(256) __nv_bfloat16 g_v2_hi[12832*512],  g_v2_lo[12832*512];
__device__ __align__(256) float g_q2[1792*512];
__device__ __align__(256) float g_a2[1280*512];
__device__ __align__(256) __nv_bfloat16 g_tqaT_hi[128*CPAD*512];
__device__ __align__(256) __nv_bfloat16 g_tqaT_lo[128*CPAD*512];
__device__ __align__(256) float g_Tbar[8192];

// ---------------- PTX helpers ----------------
__device__ __forceinline__ uint32_t smem_u32(const void* p) {
    uint32_t a;
    asm("{ .reg .u64 t; cvta.to.shared.u64 t, %1; cvt.u32.u64 %0, t; }"
        : "=r"(a) : "l"(p));
    return a;
}
__device__ __forceinline__ void mma_bf16(float* c, const uint32_t* a,
                                         const uint32_t* b) {
    asm volatile(
        "mma.sync.aligned.m16n8k16.row.col.f32.bf16.bf16.f32 "
        "{%0,%1,%2,%3}, {%4,%5,%6,%7}, {%8,%9}, {%0,%1,%2,%3};"
        : "+f"(c[0]), "+f"(c[1]), "+f"(c[2]), "+f"(c[3])
        : "r"(a[0]), "r"(a[1]), "r"(a[2]), "r"(a[3]), "r"(b[0]), "r"(b[1]));
}
__device__ __forceinline__ void ldsm4(uint32_t* r, uint32_t addr) {
    asm volatile("ldmatrix.sync.aligned.m8n8.x4.shared.b16 {%0,%1,%2,%3}, [%4];"
                 : "=r"(r[0]), "=r"(r[1]), "=r"(r[2]), "=r"(r[3]) : "r"(addr));
}
__device__ __forceinline__ void cp16(uint32_t dst, const void* src) {
    asm volatile("cp.async.cg.shared.global [%0], [%1], 16;"
                 :: "r"(dst), "l"(src));
}
__device__ __forceinline__ void cp_commit() {
    asm volatile("cp.async.commit_group;");
}
template<int N>
__device__ __forceinline__ void cp_wait() {
    asm volatile("cp.async.wait_group %0;" :: "n"(N));
}
__device__ __forceinline__ uint32_t swz_off(int row, int c) {
    return (uint32_t)(row * 64 + ((c ^ ((row >> 1) & 3)) << 4));
}

// ---------------------------------------------------------------------------
// split fp32 -> bf16 hi/lo (8 elements per thread)
// ---------------------------------------------------------------------------
__global__ void split_bf16_kernel(const float* __restrict__ x,
                                  __nv_bfloat16* __restrict__ hi,
                                  __nv_bfloat16* __restrict__ lo, int n8)
{
    int i = blockIdx.x * 256 + threadIdx.x;
    if (i >= n8) return;
    float4 v0 = ((const float4*)x)[i * 2];
    float4 v1 = ((const float4*)x)[i * 2 + 1];
    float f[8] = {v0.x, v0.y, v0.z, v0.w, v1.x, v1.y, v1.z, v1.w};
    __nv_bfloat162 H[4], L[4];
    #pragma unroll
    for (int j = 0; j < 4; j++) {
        __nv_bfloat16 h0 = __float2bfloat16(f[j*2]);
        __nv_bfloat16 h1 = __float2bfloat16(f[j*2+1]);
        H[j] = {h0, h1};
        L[j] = {__float2bfloat16(f[j*2]   - __bfloat162float(h0)),
                __float2bfloat16(f[j*2+1] - __bfloat162float(h1))};
    }
    ((uint4*)hi)[i] = *(uint4*)H;
    ((uint4*)lo)[i] = *(uint4*)L;
}

// ---------------------------------------------------------------------------
// Tbar[x] = sum_r T[r*8192 + x]
// ---------------------------------------------------------------------------
__global__ void reduce_T_kernel(const float* __restrict__ T)
{
    int x = blockIdx.x * 256 + threadIdx.x;
    float s = 0.f;
    #pragma unroll
    for (int r = 0; r < RANK; r++) s += T[(size_t)r * 8192 + x];
    g_Tbar[x] = s;
}

// ---------------------------------------------------------------------------
// HMMA bf16x3 GEMM: C[m,n] = relu( sum_k A[m,k]*W[n,k] + bias[n] )
// BM=128, BN=64, BK=32, 256 threads (8 warps 4x2, warp tile 32x32),
// 3-stage cp.async pipeline, one __syncthreads per chunk, 3 CTAs/SM.
// ---------------------------------------------------------------------------
#define STAGE_SZ 24576                 // AH 8K, AL 8K, BH 4K, BL 4K
#define GEMM_SMEM (3 * STAGE_SZ)       // 73728
#define OFF_AH 0
#define OFF_AL 8192
#define OFF_BH 16384
#define OFF_BL 20480

template<int OUT_BF16>
__global__ __launch_bounds__(256, 3)
void mma_gemm(const __nv_bfloat16* __restrict__ Ahi,
              const __nv_bfloat16* __restrict__ Alo,
              const __nv_bfloat16* __restrict__ Bhi,
              const __nv_bfloat16* __restrict__ Blo,
              const float* __restrict__ bias,
              float* __restrict__ Cf,
              __nv_bfloat16* __restrict__ Chi,
              __nv_bfloat16* __restrict__ Clo,
              int M, int N, int K)
{
    extern __shared__ char smem[];
    const uint32_t smb = smem_u32(smem);
    const int tid  = threadIdx.x;
    const int wid  = tid >> 5;
    const int lane = tid & 31;
    const int wm   = wid & 3;          // 4 warps along M (32 rows)
    const int wn   = wid >> 2;         // 2 warps along N (32 cols)
    const int bm   = blockIdx.y * 128;
    const int bn   = blockIdx.x * 64;

    const int nchunks = K >> 5;

    auto load_stage = [&](int c) {
        const uint32_t sb = smb + (uint32_t)(c % 3) * STAGE_SZ;
        const int k0 = c << 5;
        // A: 128 rows x 64B (hi+lo): 512 slots, 2 per thread
        #pragma unroll
        for (int i = 0; i < 2; i++) {
            int idx = tid + i * 256;
            int row = idx >> 2;
            int cc  = idx & 3;
            uint32_t so = swz_off(row, cc);
            size_t gA = (size_t)(bm + row) * K + k0 + cc * 8;
            cp16(sb + OFF_AH + so, Ahi + gA);
            cp16(sb + OFF_AL + so, Alo + gA);
        }
        // B: 64 rows x 64B (hi+lo): 256 slots
        {
            int row = tid >> 2;
            int cc  = tid & 3;
            uint32_t so = swz_off(row, cc);
            size_t gB = (size_t)(bn + row) * K + k0 + cc * 8;
            cp16(sb + OFF_BH + so, Bhi + gB);
            cp16(sb + OFF_BL + so, Blo + gB);
        }
    };

    float acc[2][4][4];
    #pragma unroll
    for (int mt = 0; mt < 2; mt++)
        #pragma unroll
        for (int nt = 0; nt < 4; nt++)
            #pragma unroll
            for (int i = 0; i < 4; i++) acc[mt][nt][i] = 0.f;

    const int a_r = (lane & 7) | (((lane >> 3) & 1) << 3);
    const int a_c = lane >> 4;
    const int b_r = (lane & 7) | ((lane >> 4) << 3);
    const int b_c = (lane >> 3) & 1;

    load_stage(0);
    cp_commit();
    load_stage(1);
    cp_commit();

    for (int c = 0; c < nchunks; c++) {
        cp_wait<1>();
        __syncthreads();

        if (c + 2 < nchunks) {
            load_stage(c + 2);
            cp_commit();
        } else {
            cp_commit();
        }

        const uint32_t sb = smb + (uint32_t)(c % 3) * STAGE_SZ;

        #pragma unroll
        for (int ks8 = 0; ks8 < 4; ks8 += 2) {
            uint32_t af_h[2][4], af_l[2][4];
            #pragma unroll
            for (int mt = 0; mt < 2; mt++) {
                int row = wm * 32 + mt * 16 + a_r;
                uint32_t so = swz_off(row, ks8 + a_c);
                ldsm4(af_h[mt], sb + OFF_AH + so);
                ldsm4(af_l[mt], sb + OFF_AL + so);
            }
            #pragma unroll
            for (int nq = 0; nq < 2; nq++) {
                uint32_t bf_h[4], bf_l[4];
                int row = wn * 32 + nq * 16 + b_r;
                uint32_t so = swz_off(row, ks8 + b_c);
                ldsm4(bf_h, sb + OFF_BH + so);
                ldsm4(bf_l, sb + OFF_BL + so);
                #pragma unroll
                for (int mt = 0; mt < 2; mt++)
                    #pragma unroll
                    for (int h = 0; h < 2; h++) {
                        float* ac = acc[mt][nq * 2 + h];
                        mma_bf16(ac, af_h[mt], &bf_h[h * 2]);
                        mma_bf16(ac, af_h[mt], &bf_l[h * 2]);
                        mma_bf16(ac, af_l[mt], &bf_h[h * 2]);
                    }
            }
        }
    }

    // epilogue: bias + relu
    const int g = lane >> 2;
    const int t = lane & 3;
    #pragma unroll
    for (int mt = 0; mt < 2; mt++) {
        #pragma unroll
        for (int nt = 0; nt < 4; nt++) {
            int row0 = bm + wm * 32 + mt * 16 + g;
            int row1 = row0 + 8;
            int col  = bn + wn * 32 + nt * 8 + t * 2;
            float bs0 = __ldg(bias + col), bs1 = __ldg(bias + col + 1);
            float v00 = fmaxf(acc[mt][nt][0] + bs0, 0.f);
            float v01 = fmaxf(acc[mt][nt][1] + bs1, 0.f);
            float v10 = fmaxf(acc[mt][nt][2] + bs0, 0.f);
            float v11 = fmaxf(acc[mt][nt][3] + bs1, 0.f);
            if (OUT_BF16) {
                __nv_bfloat16 h00 = __float2bfloat16(v00);
                __nv_bfloat16 h01 = __float2bfloat16(v01);
                __nv_bfloat16 h10 = __float2bfloat16(v10);
                __nv_bfloat16 h11 = __float2bfloat16(v11);
                __nv_bfloat162 H0 = {h00, h01}, H1 = {h10, h11};
                __nv_bfloat162 L0 = {
                    __float2bfloat16(v00 - __bfloat162float(h00)),
                    __float2bfloat16(v01 - __bfloat162float(h01))};
                __nv_bfloat162 L1 = {
                    __float2bfloat16(v10 - __bfloat162float(h10)),
                    __float2bfloat16(v11 - __bfloat162float(h11))};
                *(__nv_bfloat162*)(Chi + (size_t)row0 * N + col) = H0;
                *(__nv_bfloat162*)(Clo + (size_t)row0 * N + col) = L0;
                *(__nv_bfloat162*)(Chi + (size_t)row1 * N + col) = H1;
                *(__nv_bfloat162*)(Clo + (size_t)row1 * N + col) = L1;
            } else {
                *(float2*)(Cf + (size_t)row0 * N + col) = make_float2(v00, v01);
                *(float2*)(Cf + (size_t)row1 * N + col) = make_float2(v10, v11);
            }
        }
    }
}

// ---------------------------------------------------------------------------
// K7: per (b,n):  Tq = Tbar x_j q_,  Tqa = Tq x_k a_
// Writes TQA transposed as bf16 hi/lo: g_tqaT[b][c][n*16+ii], c=(q*10+a)*2+g
// ---------------------------------------------------------------------------
__global__ __launch_bounds__(256)
void tq_tqa_kernel()
{
    extern __shared__ float sm[];
    float* sT  = sm;               // 8192 (reused as sOut after step A)
    float* sQ  = sm + 8192;        // 224
    float* sA  = sm + 8416;        // 160
    float* sTq = sm + 8576;        // 7168

    const int n   = blockIdx.x;
    const int b   = blockIdx.y;
    const int tid = threadIdx.x;

    const float4* Tp = (const float4*)g_Tbar;
    for (int i = tid; i < 2048; i += 256) ((float4*)sT)[i] = Tp[i];

    if (tid < 56) {
        int q  = tid >> 2;
        int j4 = (tid & 3) << 2;
        *(float4*)&sQ[q * 16 + j4] =
            *(const float4*)(g_q2 + (size_t)(b * NQ + q) * 512 + n * 16 + j4);
    }
    if (tid >= 64 && tid < 104) {
        int t  = tid - 64;
        int a  = t >> 2;
        int k4 = (t & 3) << 2;
        *(float4*)&sA[a * 16 + k4] =
            *(const float4*)(g_a2 + (size_t)(b * NA + a) * 512 + n * 16 + k4);
    }
    __syncthreads();

    // step A: Tq[q,i,k,g]
    {
        const int i_ = tid >> 4;
        const int k_ = tid & 15;
        float accx[14], accy[14];
        #pragma unroll
        for (int q = 0; q < 14; q++) { accx[q] = 0.f; accy[q] = 0.f; }
        #pragma unroll
        for (int j = 0; j < 16; j++) {
            float2 t2 = *(const float2*)&sT[(((i_ * 16 + j) * 16) + k_) * 2];
            #pragma unroll
            for (int q = 0; q < 14; q++) {
                float qv = sQ[q * 16 + j];
                accx[q] = fmaf(t2.x, qv, accx[q]);
                accy[q] = fmaf(t2.y, qv, accy[q]);
            }
        }
        #pragma unroll
        for (int q = 0; q < 14; q++)
            *(float2*)&sTq[((q * 16 + i_) * 16 + k_) * 2] =
                make_float2(accx[q], accy[q]);
    }
    __syncthreads();

    // step B: contract with a_, stash transposed in sOut[ii][c]
    float* sOut = sT;   // [16][284]
    for (int t = tid; t < 2240; t += 256) {
        int ii  = t / 140;
        int rem = t - ii * 140;
        int q   = rem / 10;
        int a   = rem - q * 10;
        float sx = 0.f, sy = 0.f;
        #pragma unroll
        for (int k = 0; k < 16; k++) {
            float2 tq = *(const float2*)&sTq[((q * 16 + ii) * 16 + k) * 2];
            float  av = sA[a * 16 + k];
            sx = fmaf(tq.x, av, sx);
            sy = fmaf(tq.y, av, sy);
        }
        sOut[ii * 284 + rem * 2]     = sx;
        sOut[ii * 284 + rem * 2 + 1] = sy;
    }
    __syncthreads();

    for (int idx = tid; idx < 560; idx += 256) {
        int c    = idx >> 1;
        int half = idx & 1;
        __nv_bfloat162 H[4], L[4];
        #pragma unroll
        for (int j = 0; j < 4; j++) {
            float v0 = sOut[(half * 8 + j * 2)     * 284 + c];
            float v1 = sOut[(half * 8 + j * 2 + 1) * 284 + c];
            __nv_bfloat16 h0 = __float2bfloat16(v0);
            __nv_bfloat16 h1 = __float2bfloat16(v1);
            H[j] = {h0, h1};
            L[j] = {__float2bfloat16(v0 - __bfloat162float(h0)),
                    __float2bfloat16(v1 - __bfloat162float(h1))};
        }
        size_t off = ((size_t)b * CPAD + c) * 512 + n * 16 + half * 8;
        *(uint4*)(g_tqaT_hi + off) = *(uint4*)H;
        *(uint4*)(g_tqaT_lo + off) = *(uint4*)L;
    }
}

// ---------------------------------------------------------------------------
// K8 (HMMA): out[b][v][c] = sum_k V2[b*100+v][k] * TQA_T[b][c][k]
// BM=128 (100 valid), BN=96, BK=32, 256 threads, 3-stage pipeline.
// ---------------------------------------------------------------------------
#define K8_STAGE 28672
#define K8_SMEM  (3 * K8_STAGE)        // 86016
#define K8_BH    16384
#define K8_BL    22528

__global__ __launch_bounds__(256, 2)
void k8_gemm(float* __restrict__ out)
{
    extern __shared__ char smem[];
    const uint32_t smb = smem_u32(smem);
    const int tid  = threadIdx.x;
    const int wid  = tid >> 5;
    const int lane = tid & 31;
    const int wm   = wid & 3;
    const int wn   = wid >> 2;
    const int bn   = blockIdx.x * 96;
    const int b    = blockIdx.y;

    const __nv_bfloat16* Ahi = g_v2_hi + (size_t)b * 100 * 512;
    const __nv_bfloat16* Alo = g_v2_lo + (size_t)b * 100 * 512;
    const __nv_bfloat16* Bhi = g_tqaT_hi + ((size_t)b * CPAD + bn) * 512;
    const __nv_bfloat16* Blo = g_tqaT_lo + ((size_t)b * CPAD + bn) * 512;

    auto load_stage = [&](int c) {
        const uint32_t sb = smb + (uint32_t)(c % 3) * K8_STAGE;
        const int k0 = c << 5;
        #pragma unroll
        for (int i = 0; i < 2; i++) {
            int idx = tid + i * 256;
            int row = idx >> 2, cc = idx & 3;
            uint32_t so = swz_off(row, cc);
            size_t g = (size_t)row * 512 + k0 + cc * 8;
            cp16(sb + OFF_AH + so, Ahi + g);
            cp16(sb + OFF_AL + so, Alo + g);
        }
        {
            int idx = tid;
            int row = idx >> 2, cc = idx & 3;
            uint32_t so = swz_off(row, cc);
            size_t g = (size_t)row * 512 + k0 + cc * 8;
            cp16(sb + K8_BH + so, Bhi + g);
            cp16(sb + K8_BL + so, Blo + g);
        }
        if (tid < 128) {
            int idx = tid + 256;
            int row = idx >> 2, cc = idx & 3;
            uint32_t so = swz_off(row, cc);
            size_t g = (size_t)row * 512 + k0 + cc * 8;
            cp16(sb + K8_BH + so, Bhi + g);
            cp16(sb + K8_BL + so, Blo + g);
        }
    };

    float acc[2][6][4];
    #pragma unroll
    for (int mt = 0; mt < 2; mt++)
        #pragma unroll
        for (int nt = 0; nt < 6; nt++)
            #pragma unroll
            for (int i = 0; i < 4; i++) acc[mt][nt][i] = 0.f;

    const int a_r = (lane & 7) | (((lane >> 3) & 1) << 3);
    const int a_c = lane >> 4;
    const int b_r = (lane & 7) | ((lane >> 4) << 3);
    const int b_c = (lane >> 3) & 1;

    load_stage(0);
    cp_commit();
    load_stage(1);
    cp_commit();

    for (int c = 0; c < 16; c++) {
        cp_wait<1>();
        __syncthreads();

        if (c + 2 < 16) {
            load_stage(c + 2);
            cp_commit();
        } else {
            cp_commit();
        }

        const uint32_t sb = smb + (uint32_t)(c % 3) * K8_STAGE;

        #pragma unroll
        for (int ks8 = 0; ks8 < 4; ks8 += 2) {
            uint32_t af_h[2][4], af_l[2][4];
            #pragma unroll
            for (int mt = 0; mt < 2; mt++) {
                int row = wm * 32 + mt * 16 + a_r;
                uint32_t so = swz_off(row, ks8 + a_c);
                ldsm4(af_h[mt], sb + OFF_AH + so);
                ldsm4(af_l[mt], sb + OFF_AL + so);
            }
            #pragma unroll
            for (int nq = 0; nq < 3; nq++) {
                uint32_t bf_h[4], bf_l[4];
                int row = wn * 48 + nq * 16 + b_r;
                uint32_t so = swz_off(row, ks8 + b_c);
                ldsm4(bf_h, sb + K8_BH + so);
                ldsm4(bf_l, sb + K8_BL + so);
                #pragma unroll
                for (int mt = 0; mt < 2; mt++)
                    #pragma unroll
                    for (int h = 0; h < 2; h++) {
                        float* ac = acc[mt][nq * 2 + h];
                        mma_bf16(ac, af_h[mt], &bf_h[h * 2]);
                        mma_bf16(ac, af_h[mt], &bf_l[h * 2]);
                        mma_bf16(ac, af_l[mt], &bf_h[h * 2]);
                    }
            }
        }
    }

    const int g = lane >> 2;
    const int t = lane & 3;
    #pragma unroll
    for (int mt = 0; mt < 2; mt++) {
        #pragma unroll
        for (int nt = 0; nt < 6; nt++) {
            int v0 = wm * 32 + mt * 16 + g;
            int v1 = v0 + 8;
            int cg = bn + wn * 48 + nt * 8 + t * 2;
            if (cg < QAG) {
                if (v0 < NV)
                    *(float2*)(out + ((size_t)b * NV + v0) * QAG + cg) =
                        make_float2(acc[mt][nt][0], acc[mt][nt][1]);
                if (v1 < NV)
                    *(float2*)(out + ((size_t)b * NV + v1) * QAG + cg) =
                        make_float2(acc[mt][nt][2], acc[mt][nt][3]);
            }
        }
    }
}

// ---------------------------------------------------------------------------
extern "C" void kernel_launch(void* const* d_in, const int* in_sizes, int n_in,
                              void* d_out, int out_size)
{
    const float* v   = (const float*)d_in[0];
    const float* q   = (const float*)d_in[1];
    const float* a   = (const float*)d_in[2];
    const float* Wv  = (const float*)d_in[3];
    const float* bv  = (const float*)d_in[4];
    const float* Wq  = (const float*)d_in[5];
    const float* bq  = (const float*)d_in[6];
    const float* Wa  = (const float*)d_in[7];
    const float* ba  = (const float*)d_in[8];
    const float* Wvr = (const float*)d_in[9];
    const float* bvr = (const float*)d_in[10];
    const float* Wqr = (const float*)d_in[11];
    const float* bqr = (const float*)d_in[12];
    const float* War = (const float*)d_in[13];
    const float* bar = (const float*)d_in[14];
    const float* T   = (const float*)d_in[15];
    float* out       = (float*)d_out;

    __nv_bfloat16 *vhi,*vlo,*qhi,*qlo,*ahi,*alo;
    __nv_bfloat16 *Wvhi,*Wvlo,*Wqhi,*Wqlo,*Wahi,*Walo;
    __nv_bfloat16 *Wvrhi,*Wvrlo,*Wqrhi,*Wqrlo,*Warhi,*Warlo;
    __nv_bfloat16 *vthi,*vtlo,*qthi,*qtlo,*athi,*atlo,*v2hi,*v2lo;
    float *pq2,*pa2;
    cudaGetSymbolAddress((void**)&vhi, g_v_hi);   cudaGetSymbolAddress((void**)&vlo, g_v_lo);
    cudaGetSymbolAddress((void**)&qhi, g_q_hi);   cudaGetSymbolAddress((void**)&qlo, g_q_lo);
    cudaGetSymbolAddress((void**)&ahi, g_a_hi);   cudaGetSymbolAddress((void**)&alo, g_a_lo);
    cudaGetSymbolAddress((void**)&Wvhi, g_Wv_hi); cudaGetSymbolAddress((void**)&Wvlo, g_Wv_lo);
    cudaGetSymbolAddress((void**)&Wqhi, g_Wq_hi); cudaGetSymbolAddress((void**)&Wqlo, g_Wq_lo);
    cudaGetSymbolAddress((void**)&Wahi, g_Wa_hi); cudaGetSymbolAddress((void**)&Walo, g_Wa_lo);
    cudaGetSymbolAddress((void**)&Wvrhi, g_Wvr_hi); cudaGetSymbolAddress((void**)&Wvrlo, g_Wvr_lo);
    cudaGetSymbolAddress((void**)&Wqrhi, g_Wqr_hi); cudaGetSymbolAddress((void**)&Wqrlo, g_Wqr_lo);
    cudaGetSymbolAddress((void**)&Warhi, g_War_hi); cudaGetSymbolAddress((void**)&Warlo, g_War_lo);
    cudaGetSymbolAddress((void**)&vthi, g_vt_hi); cudaGetSymbolAddress((void**)&vtlo, g_vt_lo);
    cudaGetSymbolAddress((void**)&qthi, g_qt_hi); cudaGetSymbolAddress((void**)&qtlo, g_qt_lo);
    cudaGetSymbolAddress((void**)&athi, g_at_hi); cudaGetSymbolAddress((void**)&atlo, g_at_lo);
    cudaGetSymbolAddress((void**)&v2hi, g_v2_hi); cudaGetSymbolAddress((void**)&v2lo, g_v2_lo);
    cudaGetSymbolAddress((void**)&pq2, g_q2);
    cudaGetSymbolAddress((void**)&pa2, g_a2);

    cudaFuncSetAttribute(mma_gemm<0>, cudaFuncAttributeMaxDynamicSharedMemorySize, GEMM_SMEM);
    cudaFuncSetAttribute(mma_gemm<1>, cudaFuncAttributeMaxDynamicSharedMemorySize, GEMM_SMEM);
    cudaFuncSetAttribute(tq_tqa_kernel, cudaFuncAttributeMaxDynamicSharedMemorySize, 62976);
    cudaFuncSetAttribute(k8_gemm, cudaFuncAttributeMaxDynamicSharedMemorySize, K8_SMEM);

    auto split = [&](const float* x, __nv_bfloat16* h, __nv_bfloat16* l, int n) {
        int n8 = n / 8;
        split_bf16_kernel<<<(n8 + 255) / 256, 256>>>(x, h, l, n8);
    };

    // launches 1-3: inputs for the big GEMM
    split(v,   vhi,   vlo,   12800 * 2048);
    split(Wv,  Wvhi,  Wvlo,  512 * 2048);
    split(q,   qhi,   qlo,   1792  * 1024);

    // launch 4: stage-1 v projection (gets ncu-profiled)
    mma_gemm<1><<<dim3(8,100), 256, GEMM_SMEM>>>(vhi, vlo, Wvhi, Wvlo, bv,
                                                 nullptr, vthi, vtlo, 12800, 512, 2048);

    split(a,   ahi,   alo,   1280  * 1024);
    split(Wq,  Wqhi,  Wqlo,  512 * 1024);
    split(Wa,  Wahi,  Walo,  512 * 1024);
    split(Wvr, Wvrhi, Wvrlo, 512 * 512);
    split(Wqr, Wqrhi, Wqrlo, 512 * 512);
    split(War, Warhi, Warlo, 512 * 512);
    reduce_T_kernel<<<32, 256>>>(T);

    // stage 1 (q, a)
    mma_gemm<1><<<dim3(8,14), 256, GEMM_SMEM>>>(qhi, qlo, Wqhi, Wqlo, bq,
                                                nullptr, qthi, qtlo, 1792, 512, 1024);
    mma_gemm<1><<<dim3(8,10), 256, GEMM_SMEM>>>(ahi, alo, Wahi, Walo, ba,
                                                nullptr, athi, atlo, 1280, 512, 1024);

    // stage 2
    mma_gemm<1><<<dim3(8,100), 256, GEMM_SMEM>>>(vthi, vtlo, Wvrhi, Wvrlo, bvr,
                                                 nullptr, v2hi, v2lo, 12800, 512, 512);
    mma_gemm<0><<<dim3(8,14),  256, GEMM_SMEM>>>(qthi, qtlo, Wqrhi, Wqrlo, bqr,
                                                 pq2, nullptr, nullptr, 1792, 512, 512);
    mma_gemm<0><<<dim3(8,10),  256, GEMM_SMEM>>>(athi, atlo, Warhi, Warlo, bar,
                                                 pa2, nullptr, nullptr, 1280, 512, 512);

    // stage 3: Tucker core contraction -> TQA_T (bf16 hi/lo)
    tq_tqa_kernel<<<dim3(RANK, Bb), 256, 62976>>>();

    // stage 4: batched HMMA GEMM -> output
    k8_gemm<<<dim3(3, Bb), 256, K8_SMEM>>>(out);
}

// round 12
// speedup vs baseline: 1.1905x; 1.1371x over previous
#include <cuda_runtime.h>
#include <cuda_bf16.h>
#include <cstdint>

// ---------------------------------------------------------------------------
// TCNet: B=128, NV=100, NQ=14, NA=10, V_DIM=2048, Q_DIM=1024, A_DIM=1024,
//        H_DIM=512, RANK=32, HD=16, G=2
//
// einsum 'rijkg,bnvi,bnqj,bnak->bvqag' : r and n are INDEPENDENT sums.
//   Tbar[i,j,k,g] = sum_r T[r,i,j,k,g]
//   out[b,v,q,a,g] = sum_{n,i,j,k} Tbar v_ q_ a_
//
// HMMA bf16x3 fp32 emulation (hi*hi + hi*lo + lo*hi).
// This round: GROUPED GEMM launches (stage-1: v+q+a in one grid, stage-2
// likewise) to fill tail waves; all 9 fp32->bf16 splits fused in one launch.
// GEMM mainloop = R9 best config: BM=128 BN=128 BK=32, 8 warps (32x64),
// 3-stage cp.async, 2 CTAs/SM.
// ---------------------------------------------------------------------------

#define Bb    128
#define NV    100
#define NQ    14
#define NA    10
#define RANK  32
#define G     2
#define QAG   (NQ*NA*G)   // 280
#define CPAD  288

// ---------------- scratch (static device globals, zero-initialized) --------
__device__ __align__(256) __nv_bfloat16 g_v_hi [12800*2048], g_v_lo [12800*2048];
__device__ __align__(256) __nv_bfloat16 g_q_hi [1792*1024],  g_q_lo [1792*1024];
__device__ __align__(256) __nv_bfloat16 g_a_hi [1280*1024],  g_a_lo [1280*1024];
__device__ __align__(256) __nv_bfloat16 g_Wv_hi[512*2048],   g_Wv_lo[512*2048];
__device__ __align__(256) __nv_bfloat16 g_Wq_hi[512*1024],   g_Wq_lo[512*1024];
__device__ __align__(256) __nv_bfloat16 g_Wa_hi[512*1024],   g_Wa_lo[512*1024];
__device__ __align__(256) __nv_bfloat16 g_Wvr_hi[512*512],   g_Wvr_lo[512*512];
__device__ __align__(256) __nv_bfloat16 g_Wqr_hi[512*512],   g_Wqr_lo[512*512];
__device__ __align__(256) __nv_bfloat16 g_War_hi[512*512],   g_War_lo[512*512];
__device__ __align__(256) __nv_bfloat16 g_vt_hi[12800*512],  g_vt_lo[12800*512];
__device__ __align__(256) __nv_bfloat16 g_qt_hi[1792*512],   g_qt_lo[1792*512];
__device__ __align__(256) __nv_bfloat16 g_at_hi[1280*512],   g_at_lo[1280*512];
__device__ __align__(256) __nv_bfloat16 g_v2_hi[12832*512],  g_v2_lo[12832*512];
__device__ __align__(256) float g_q2[1792*512];
__device__ __align__(256) float g_a2[1280*512];
__device__ __align__(256) __nv_bfloat16 g_tqaT_hi[128*CPAD*512];
__device__ __align__(256) __nv_bfloat16 g_tqaT_lo[128*CPAD*512];
__device__ __align__(256) float g_Tbar[8192];

// ---------------- PTX helpers ----------------
__device__ __forceinline__ uint32_t smem_u32(const void* p) {
    uint32_t a;
    asm("{ .reg .u64 t; cvta.to.shared.u64 t, %1; cvt.u32.u64 %0, t; }"
        : "=r"(a) : "l"(p));
    return a;
}
__device__ __forceinline__ void mma_bf16(float* c, const uint32_t* a,
                                         const uint32_t* b) {
    asm volatile(
        "mma.sync.aligned.m16n8k16.row.col.f32.bf16.bf16.f32 "
        "{%0,%1,%2,%3}, {%4,%5,%6,%7}, {%8,%9}, {%0,%1,%2,%3};"
        : "+f"(c[0]), "+f"(c[1]), "+f"(c[2]), "+f"(c[3])
        : "r"(a[0]), "r"(a[1]), "r"(a[2]), "r"(a[3]), "r"(b[0]), "r"(b[1]));
}
__device__ __forceinline__ void ldsm4(uint32_t* r, uint32_t addr) {
    asm volatile("ldmatrix.sync.aligned.m8n8.x4.shared.b16 {%0,%1,%2,%3}, [%4];"
                 : "=r"(r[0]), "=r"(r[1]), "=r"(r[2]), "=r"(r[3]) : "r"(addr));
}
__device__ __forceinline__ void cp16(uint32_t dst, const void* src) {
    asm volatile("cp.async.cg.shared.global [%0], [%1], 16;"
                 :: "r"(dst), "l"(src));
}
__device__ __forceinline__ void cp_commit() {
    asm volatile("cp.async.commit_group;");
}
template<int N>
__device__ __forceinline__ void cp_wait() {
    asm volatile("cp.async.wait_group %0;" :: "n"(N));
}
__device__ __forceinline__ uint32_t swz_off(int row, int c) {
    return (uint32_t)(row * 64 + ((c ^ ((row >> 1) & 3)) << 4));
}

// ---------------------------------------------------------------------------
// Fused split: all 9 fp32 -> bf16 hi/lo conversions in one grid.
// 8 elements per thread over a concatenated index space.
// ---------------------------------------------------------------------------
#define R_V    0
#define R_Q    3276800
#define R_A    3506176
#define R_WV   3670016
#define R_WQ   3801088
#define R_WA   3866624
#define R_WVR  3932160
#define R_WQR  3964928
#define R_WAR  3997696
#define R_END  4030464

__device__ __forceinline__ void split8(const float* __restrict__ src,
                                       __nv_bfloat16* __restrict__ hi,
                                       __nv_bfloat16* __restrict__ lo, int i)
{
    float4 v0 = ((const float4*)src)[i * 2];
    float4 v1 = ((const float4*)src)[i * 2 + 1];
    float f[8] = {v0.x, v0.y, v0.z, v0.w, v1.x, v1.y, v1.z, v1.w};
    __nv_bfloat162 H[4], L[4];
    #pragma unroll
    for (int j = 0; j < 4; j++) {
        __nv_bfloat16 h0 = __float2bfloat16(f[j*2]);
        __nv_bfloat16 h1 = __float2bfloat16(f[j*2+1]);
        H[j] = {h0, h1};
        L[j] = {__float2bfloat16(f[j*2]   - __bfloat162float(h0)),
                __float2bfloat16(f[j*2+1] - __bfloat162float(h1))};
    }
    ((uint4*)hi)[i] = *(uint4*)H;
    ((uint4*)lo)[i] = *(uint4*)L;
}

__global__ void fused_split_kernel(const float* __restrict__ v,
                                   const float* __restrict__ q,
                                   const float* __restrict__ a,
                                   const float* __restrict__ Wv,
                                   const float* __restrict__ Wq,
                                   const float* __restrict__ Wa,
                                   const float* __restrict__ Wvr,
                                   const float* __restrict__ Wqr,
                                   const float* __restrict__ War)
{
    int gi = blockIdx.x * 256 + threadIdx.x;
    if (gi >= R_END) return;
    if      (gi < R_Q)   split8(v,   g_v_hi,   g_v_lo,   gi - R_V);
    else if (gi < R_A)   split8(q,   g_q_hi,   g_q_lo,   gi - R_Q);
    else if (gi < R_WV)  split8(a,   g_a_hi,   g_a_lo,   gi - R_A);
    else if (gi < R_WQ)  split8(Wv,  g_Wv_hi,  g_Wv_lo,  gi - R_WV);
    else if (gi < R_WA)  split8(Wq,  g_Wq_hi,  g_Wq_lo,  gi - R_WQ);
    else if (gi < R_WVR) split8(Wa,  g_Wa_hi,  g_Wa_lo,  gi - R_WA);
    else if (gi < R_WQR) split8(Wvr, g_Wvr_hi, g_Wvr_lo, gi - R_WVR);
    else if (gi < R_WAR) split8(Wqr, g_Wqr_hi, g_Wqr_lo, gi - R_WQR);
    else                 split8(War, g_War_hi, g_War_lo, gi - R_WAR);
}

// ---------------------------------------------------------------------------
// Tbar[x] = sum_r T[r*8192 + x]
// ---------------------------------------------------------------------------
__global__ void reduce_T_kernel(const float* __restrict__ T)
{
    int x = blockIdx.x * 256 + threadIdx.x;
    float s = 0.f;
    #pragma unroll
    for (int r = 0; r < RANK; r++) s += T[(size_t)r * 8192 + x];
    g_Tbar[x] = s;
}

// ---------------------------------------------------------------------------
// Grouped HMMA bf16x3 GEMM.  STAGE=1: {v,q,a} modality projections, all
// bf16 hi/lo out.  STAGE=2: {v,q,a} rank projections, v->bf16, q/a->fp32.
// Grid 496 linear: [0,400) v tiles, [400,456) q, [456,496) a.
// BM=128, BN=128, BK=32, 8 warps (32x64), 3-stage cp.async, 2 CTAs/SM.
// ---------------------------------------------------------------------------
#define STAGE_SZ 32768
#define GEMM_SMEM (3 * STAGE_SZ)       // 98304
#define OFF_AH 0
#define OFF_AL 8192
#define OFF_BH 16384
#define OFF_BL 24576
#define HN 512                          // N is 512 for every problem

template<int STAGE>
__global__ __launch_bounds__(256, 2)
void grouped_gemm(const float* __restrict__ bias_v,
                  const float* __restrict__ bias_q,
                  const float* __restrict__ bias_a)
{
    extern __shared__ char smem[];
    const uint32_t smb = smem_u32(smem);
    const int tid  = threadIdx.x;
    const int wid  = tid >> 5;
    const int lane = tid & 31;
    const int wm   = wid & 3;
    const int wn   = wid >> 2;
    const int id   = blockIdx.x;

    // ---- problem dispatch (uniform per CTA) ----
    const __nv_bfloat16 *Ahi, *Alo, *Bhi, *Blo;
    const float* bias;
    __nv_bfloat16 *Chi = nullptr, *Clo = nullptr;
    float* Cf = nullptr;
    int K, pid;
    bool outbf;

    if (STAGE == 1) {
        outbf = true;
        if (id < 400) {
            pid = id;       Ahi = g_v_hi; Alo = g_v_lo;
            Bhi = g_Wv_hi;  Blo = g_Wv_lo; K = 2048; bias = bias_v;
            Chi = g_vt_hi;  Clo = g_vt_lo;
        } else if (id < 456) {
            pid = id - 400; Ahi = g_q_hi; Alo = g_q_lo;
            Bhi = g_Wq_hi;  Blo = g_Wq_lo; K = 1024; bias = bias_q;
            Chi = g_qt_hi;  Clo = g_qt_lo;
        } else {
            pid = id - 456; Ahi = g_a_hi; Alo = g_a_lo;
            Bhi = g_Wa_hi;  Blo = g_Wa_lo; K = 1024; bias = bias_a;
            Chi = g_at_hi;  Clo = g_at_lo;
        }
    } else {
        K = 512;
        if (id < 400) {
            pid = id;       Ahi = g_vt_hi; Alo = g_vt_lo;
            Bhi = g_Wvr_hi; Blo = g_Wvr_lo; bias = bias_v;
            Chi = g_v2_hi;  Clo = g_v2_lo; outbf = true;
        } else if (id < 456) {
            pid = id - 400; Ahi = g_qt_hi; Alo = g_qt_lo;
            Bhi = g_Wqr_hi; Blo = g_Wqr_lo; bias = bias_q;
            Cf = g_q2; outbf = false;
        } else {
            pid = id - 456; Ahi = g_at_hi; Alo = g_at_lo;
            Bhi = g_War_hi; Blo = g_War_lo; bias = bias_a;
            Cf = g_a2; outbf = false;
        }
    }
    const int bm = (pid >> 2) * 128;
    const int bn = (pid & 3) * 128;
    const int nchunks = K >> 5;

    auto load_stage = [&](int c) {
        const uint32_t sb = smb + (uint32_t)(c % 3) * STAGE_SZ;
        const int k0 = c << 5;
        #pragma unroll
        for (int i = 0; i < 2; i++) {
            int idx = tid + i * 256;
            int row = idx >> 2;
            int cc  = idx & 3;
            uint32_t so = swz_off(row, cc);
            size_t gA = (size_t)(bm + row) * K + k0 + cc * 8;
            size_t gB = (size_t)(bn + row) * K + k0 + cc * 8;
            cp16(sb + OFF_AH + so, Ahi + gA);
            cp16(sb + OFF_AL + so, Alo + gA);
            cp16(sb + OFF_BH + so, Bhi + gB);
            cp16(sb + OFF_BL + so, Blo + gB);
        }
    };

    float acc[2][8][4];
    #pragma unroll
    for (int mt = 0; mt < 2; mt++)
        #pragma unroll
        for (int nt = 0; nt < 8; nt++)
            #pragma unroll
            for (int i = 0; i < 4; i++) acc[mt][nt][i] = 0.f;

    const int a_r = (lane & 7) | (((lane >> 3) & 1) << 3);
    const int a_c = lane >> 4;
    const int b_r = (lane & 7) | ((lane >> 4) << 3);
    const int b_c = (lane >> 3) & 1;

    load_stage(0);
    cp_commit();
    load_stage(1);
    cp_commit();

    for (int c = 0; c < nchunks; c++) {
        cp_wait<1>();
        __syncthreads();

        if (c + 2 < nchunks) {
            load_stage(c + 2);
            cp_commit();
        } else {
            cp_commit();
        }

        const uint32_t sb = smb + (uint32_t)(c % 3) * STAGE_SZ;

        #pragma unroll
        for (int ks8 = 0; ks8 < 4; ks8 += 2) {
            uint32_t af_h[2][4], af_l[2][4];
            #pragma unroll
            for (int mt = 0; mt < 2; mt++) {
                int row = wm * 32 + mt * 16 + a_r;
                uint32_t so = swz_off(row, ks8 + a_c);
                ldsm4(af_h[mt], sb + OFF_AH + so);
                ldsm4(af_l[mt], sb + OFF_AL + so);
            }
            #pragma unroll
            for (int nq = 0; nq < 4; nq++) {
                uint32_t bf_h[4], bf_l[4];
                int row = wn * 64 + nq * 16 + b_r;
                uint32_t so = swz_off(row, ks8 + b_c);
                ldsm4(bf_h, sb + OFF_BH + so);
                ldsm4(bf_l, sb + OFF_BL + so);
                #pragma unroll
                for (int mt = 0; mt < 2; mt++)
                    #pragma unroll
                    for (int h = 0; h < 2; h++) {
                        float* ac = acc[mt][nq * 2 + h];
                        mma_bf16(ac, af_h[mt], &bf_h[h * 2]);
                        mma_bf16(ac, af_h[mt], &bf_l[h * 2]);
                        mma_bf16(ac, af_l[mt], &bf_h[h * 2]);
                    }
            }
        }
    }

    // epilogue: bias + relu
    const int g = lane >> 2;
    const int t = lane & 3;
    #pragma unroll
    for (int mt = 0; mt < 2; mt++) {
        #pragma unroll
        for (int nt = 0; nt < 8; nt++) {
            int row0 = bm + wm * 32 + mt * 16 + g;
            int row1 = row0 + 8;
            int col  = bn + wn * 64 + nt * 8 + t * 2;
            float bs0 = __ldg(bias + col), bs1 = __ldg(bias + col + 1);
            float v00 = fmaxf(acc[mt][nt][0] + bs0, 0.f);
            float v01 = fmaxf(acc[mt][nt][1] + bs1, 0.f);
            float v10 = fmaxf(acc[mt][nt][2] + bs0, 0.f);
            float v11 = fmaxf(acc[mt][nt][3] + bs1, 0.f);
            if (outbf) {
                __nv_bfloat16 h00 = __float2bfloat16(v00);
                __nv_bfloat16 h01 = __float2bfloat16(v01);
                __nv_bfloat16 h10 = __float2bfloat16(v10);
                __nv_bfloat16 h11 = __float2bfloat16(v11);
                __nv_bfloat162 H0 = {h00, h01}, H1 = {h10, h11};
                __nv_bfloat162 L0 = {
                    __float2bfloat16(v00 - __bfloat162float(h00)),
                    __float2bfloat16(v01 - __bfloat162float(h01))};
                __nv_bfloat162 L1 = {
                    __float2bfloat16(v10 - __bfloat162float(h10)),
                    __float2bfloat16(v11 - __bfloat162float(h11))};
                *(__nv_bfloat162*)(Chi + (size_t)row0 * HN + col) = H0;
                *(__nv_bfloat162*)(Clo + (size_t)row0 * HN + col) = L0;
                *(__nv_bfloat162*)(Chi + (size_t)row1 * HN + col) = H1;
                *(__nv_bfloat162*)(Clo + (size_t)row1 * HN + col) = L1;
            } else {
                *(float2*)(Cf + (size_t)row0 * HN + col) = make_float2(v00, v01);
                *(float2*)(Cf + (size_t)row1 * HN + col) = make_float2(v10, v11);
            }
        }
    }
}

// ---------------------------------------------------------------------------
// K7: per (b,n):  Tq = Tbar x_j q_,  Tqa = Tq x_k a_
// Writes TQA transposed as bf16 hi/lo: g_tqaT[b][c][n*16+ii], c=(q*10+a)*2+g
// ---------------------------------------------------------------------------
__global__ __launch_bounds__(256)
void tq_tqa_kernel()
{
    extern __shared__ float sm[];
    float* sT  = sm;               // 8192 (reused as sOut after step A)
    float* sQ  = sm + 8192;        // 224
    float* sA  = sm + 8416;        // 160
    float* sTq = sm + 8576;        // 7168

    const int n   = blockIdx.x;
    const int b   = blockIdx.y;
    const int tid = threadIdx.x;

    const float4* Tp = (const float4*)g_Tbar;
    for (int i = tid; i < 2048; i += 256) ((float4*)sT)[i] = Tp[i];

    if (tid < 56) {
        int q  = tid >> 2;
        int j4 = (tid & 3) << 2;
        *(float4*)&sQ[q * 16 + j4] =
            *(const float4*)(g_q2 + (size_t)(b * NQ + q) * 512 + n * 16 + j4);
    }
    if (tid >= 64 && tid < 104) {
        int t  = tid - 64;
        int a  = t >> 2;
        int k4 = (t & 3) << 2;
        *(float4*)&sA[a * 16 + k4] =
            *(const float4*)(g_a2 + (size_t)(b * NA + a) * 512 + n * 16 + k4);
    }
    __syncthreads();

    // step A: Tq[q,i,k,g]
    {
        const int i_ = tid >> 4;
        const int k_ = tid & 15;
        float accx[14], accy[14];
        #pragma unroll
        for (int q = 0; q < 14; q++) { accx[q] = 0.f; accy[q] = 0.f; }
        #pragma unroll
        for (int j = 0; j < 16; j++) {
            float2 t2 = *(const float2*)&sT[(((i_ * 16 + j) * 16) + k_) * 2];
            #pragma unroll
            for (int q = 0; q < 14; q++) {
                float qv = sQ[q * 16 + j];
                accx[q] = fmaf(t2.x, qv, accx[q]);
                accy[q] = fmaf(t2.y, qv, accy[q]);
            }
        }
        #pragma unroll
        for (int q = 0; q < 14; q++)
            *(float2*)&sTq[((q * 16 + i_) * 16 + k_) * 2] =
                make_float2(accx[q], accy[q]);
    }
    __syncthreads();

    // step B: contract with a_, stash transposed in sOut[ii][c]
    float* sOut = sT;   // [16][284]
    for (int t = tid; t < 2240; t += 256) {
        int ii  = t / 140;
        int rem = t - ii * 140;
        int q   = rem / 10;
        int a   = rem - q * 10;
        float sx = 0.f, sy = 0.f;
        #pragma unroll
        for (int k = 0; k < 16; k++) {
            float2 tq = *(const float2*)&sTq[((q * 16 + ii) * 16 + k) * 2];
            float  av = sA[a * 16 + k];
            sx = fmaf(tq.x, av, sx);
            sy = fmaf(tq.y, av, sy);
        }
        sOut[ii * 284 + rem * 2]     = sx;
        sOut[ii * 284 + rem * 2 + 1] = sy;
    }
    __syncthreads();

    for (int idx = tid; idx < 560; idx += 256) {
        int c    = idx >> 1;
        int half = idx & 1;
        __nv_bfloat162 H[4], L[4];
        #pragma unroll
        for (int j = 0; j < 4; j++) {
            float v0 = sOut[(half * 8 + j * 2)     * 284 + c];
            float v1 = sOut[(half * 8 + j * 2 + 1) * 284 + c];
            __nv_bfloat16 h0 = __float2bfloat16(v0);
            __nv_bfloat16 h1 = __float2bfloat16(v1);
            H[j] = {h0, h1};
            L[j] = {__float2bfloat16(v0 - __bfloat162float(h0)),
                    __float2bfloat16(v1 - __bfloat162float(h1))};
        }
        size_t off = ((size_t)b * CPAD + c) * 512 + n * 16 + half * 8;
        *(uint4*)(g_tqaT_hi + off) = *(uint4*)H;
        *(uint4*)(g_tqaT_lo + off) = *(uint4*)L;
    }
}

// ---------------------------------------------------------------------------
// K8 (HMMA): out[b][v][c] = sum_k V2[b*100+v][k] * TQA_T[b][c][k]
// BM=128 (100 valid), BN=96, BK=32, 256 threads, 3-stage pipeline.
// ---------------------------------------------------------------------------
#define K8_STAGE 28672
#define K8_SMEM  (3 * K8_STAGE)
#define K8_BH    16384
#define K8_BL    22528

__global__ __launch_bounds__(256, 2)
void k8_gemm(float* __restrict__ out)
{
    extern __shared__ char smem[];
    const uint32_t smb = smem_u32(smem);
    const int tid  = threadIdx.x;
    const int wid  = tid >> 5;
    const int lane = tid & 31;
    const int wm   = wid & 3;
    const int wn   = wid >> 2;
    const int bn   = blockIdx.x * 96;
    const int b    = blockIdx.y;

    const __nv_bfloat16* Ahi = g_v2_hi + (size_t)b * 100 * 512;
    const __nv_bfloat16* Alo = g_v2_lo + (size_t)b * 100 * 512;
    const __nv_bfloat16* Bhi = g_tqaT_hi + ((size_t)b * CPAD + bn) * 512;
    const __nv_bfloat16* Blo = g_tqaT_lo + ((size_t)b * CPAD + bn) * 512;

    auto load_stage = [&](int c) {
        const uint32_t sb = smb + (uint32_t)(c % 3) * K8_STAGE;
        const int k0 = c << 5;
        #pragma unroll
        for (int i = 0; i < 2; i++) {
            int idx = tid + i * 256;
            int row = idx >> 2, cc = idx & 3;
            uint32_t so = swz_off(row, cc);
            size_t g = (size_t)row * 512 + k0 + cc * 8;
            cp16(sb + OFF_AH + so, Ahi + g);
            cp16(sb + OFF_AL + so, Alo + g);
        }
        {
            int row = tid >> 2, cc = tid & 3;
            uint32_t so = swz_off(row, cc);
            size_t g = (size_t)row * 512 + k0 + cc * 8;
            cp16(sb + K8_BH + so, Bhi + g);
            cp16(sb + K8_BL + so, Blo + g);
        }
        if (tid < 128) {
            int idx = tid + 256;
            int row = idx >> 2, cc = idx & 3;
            uint32_t so = swz_off(row, cc);
            size_t g = (size_t)row * 512 + k0 + cc * 8;
            cp16(sb + K8_BH + so, Bhi + g);
            cp16(sb + K8_BL + so, Blo + g);
        }
    };

    float acc[2][6][4];
    #pragma unroll
    for (int mt = 0; mt < 2; mt++)
        #pragma unroll
        for (int nt = 0; nt < 6; nt++)
            #pragma unroll
            for (int i = 0; i < 4; i++) acc[mt][nt][i] = 0.f;

    const int a_r = (lane & 7) | (((lane >> 3) & 1) << 3);
    const int a_c = lane >> 4;
    const int b_r = (lane & 7) | ((lane >> 4) << 3);
    const int b_c = (lane >> 3) & 1;

    load_stage(0);
    cp_commit();
    load_stage(1);
    cp_commit();

    for (int c = 0; c < 16; c++) {
        cp_wait<1>();
        __syncthreads();

        if (c + 2 < 16) {
            load_stage(c + 2);
            cp_commit();
        } else {
            cp_commit();
        }

        const uint32_t sb = smb + (uint32_t)(c % 3) * K8_STAGE;

        #pragma unroll
        for (int ks8 = 0; ks8 < 4; ks8 += 2) {
            uint32_t af_h[2][4], af_l[2][4];
            #pragma unroll
            for (int mt = 0; mt < 2; mt++) {
                int row = wm * 32 + mt * 16 + a_r;
                uint32_t so = swz_off(row, ks8 + a_c);
                ldsm4(af_h[mt], sb + OFF_AH + so);
                ldsm4(af_l[mt], sb + OFF_AL + so);
            }
            #pragma unroll
            for (int nq = 0; nq < 3; nq++) {
                uint32_t bf_h[4], bf_l[4];
                int row = wn * 48 + nq * 16 + b_r;
                uint32_t so = swz_off(row, ks8 + b_c);
                ldsm4(bf_h, sb + K8_BH + so);
                ldsm4(bf_l, sb + K8_BL + so);
                #pragma unroll
                for (int mt = 0; mt < 2; mt++)
                    #pragma unroll
                    for (int h = 0; h < 2; h++) {
                        float* ac = acc[mt][nq * 2 + h];
                        mma_bf16(ac, af_h[mt], &bf_h[h * 2]);
                        mma_bf16(ac, af_h[mt], &bf_l[h * 2]);
                        mma_bf16(ac, af_l[mt], &bf_h[h * 2]);
                    }
            }
        }
    }

    const int g = lane >> 2;
    const int t = lane & 3;
    #pragma unroll
    for (int mt = 0; mt < 2; mt++) {
        #pragma unroll
        for (int nt = 0; nt < 6; nt++) {
            int v0 = wm * 32 + mt * 16 + g;
            int v1 = v0 + 8;
            int cg = bn + wn * 48 + nt * 8 + t * 2;
            if (cg < QAG) {
                if (v0 < NV)
                    *(float2*)(out + ((size_t)b * NV + v0) * QAG + cg) =
                        make_float2(acc[mt][nt][0], acc[mt][nt][1]);
                if (v1 < NV)
                    *(float2*)(out + ((size_t)b * NV + v1) * QAG + cg) =
                        make_float2(acc[mt][nt][2], acc[mt][nt][3]);
            }
        }
    }
}

// ---------------------------------------------------------------------------
extern "C" void kernel_launch(void* const* d_in, const int* in_sizes, int n_in,
                              void* d_out, int out_size)
{
    const float* v   = (const float*)d_in[0];
    const float* q   = (const float*)d_in[1];
    const float* a   = (const float*)d_in[2];
    const float* Wv  = (const float*)d_in[3];
    const float* bv  = (const float*)d_in[4];
    const float* Wq  = (const float*)d_in[5];
    const float* bq  = (const float*)d_in[6];
    const float* Wa  = (const float*)d_in[7];
    const float* ba  = (const float*)d_in[8];
    const float* Wvr = (const float*)d_in[9];
    const float* bvr = (const float*)d_in[10];
    const float* Wqr = (const float*)d_in[11];
    const float* bqr = (const float*)d_in[12];
    const float* War = (const float*)d_in[13];
    const float* bar = (const float*)d_in[14];
    const float* T   = (const float*)d_in[15];
    float* out       = (float*)d_out;

    cudaFuncSetAttribute(grouped_gemm<1>, cudaFuncAttributeMaxDynamicSharedMemorySize, GEMM_SMEM);
    cudaFuncSetAttribute(grouped_gemm<2>, cudaFuncAttributeMaxDynamicSharedMemorySize, GEMM_SMEM);
    cudaFuncSetAttribute(tq_tqa_kernel, cudaFuncAttributeMaxDynamicSharedMemorySize, 62976);
    cudaFuncSetAttribute(k8_gemm, cudaFuncAttributeMaxDynamicSharedMemorySize, K8_SMEM);

    // 1: all fp32 -> bf16 hi/lo splits in one launch
    fused_split_kernel<<<(R_END + 255) / 256, 256>>>(v, q, a, Wv, Wq, Wa,
                                                     Wvr, Wqr, War);
    // 2: reduce T over rank
    reduce_T_kernel<<<32, 256>>>(T);

    // 3: grouped stage-1 (v + q + a modality projections)
    grouped_gemm<1><<<496, 256, GEMM_SMEM>>>(bv, bq, ba);

    // 4: grouped stage-2 (rank projections)  [ncu-profiled position]
    grouped_gemm<2><<<496, 256, GEMM_SMEM>>>(bvr, bqr, bar);

    // 5: Tucker core contraction -> TQA_T (bf16 hi/lo)
    tq_tqa_kernel<<<dim3(RANK, Bb), 256, 62976>>>();

    // 6: batched final GEMM -> output
    k8_gemm<<<dim3(3, Bb), 256, K8_SMEM>>>(out);
}

// round 13
// speedup vs baseline: 1.2027x; 1.0103x over previous
#include <cuda_runtime.h>
#include <cuda_bf16.h>
#include <cstdint>

// ---------------------------------------------------------------------------
// TCNet: B=128, NV=100, NQ=14, NA=10, V_DIM=2048, Q_DIM=1024, A_DIM=1024,
//        H_DIM=512, RANK=32, HD=16, G=2
//
// einsum 'rijkg,bnvi,bnqj,bnak->bvqag' : r and n are INDEPENDENT sums.
//   Tbar[i,j,k,g] = sum_r T[r,i,j,k,g]
//   out[b,v,q,a,g] = sum_{n,i,j,k} Tbar v_ q_ a_
//
// HMMA bf16x3 fp32 emulation (hi*hi + hi*lo + lo*hi), grouped GEMM launches.
// This round: term-major MMA ordering (all-hh, all-hl, all-lh per ks8 step)
// to break the 3-deep serial accumulator chains.
// ---------------------------------------------------------------------------

#define Bb    128
#define NV    100
#define NQ    14
#define NA    10
#define RANK  32
#define G     2
#define QAG   (NQ*NA*G)   // 280
#define CPAD  288

// ---------------- scratch (static device globals, zero-initialized) --------
__device__ __align__(256) __nv_bfloat16 g_v_hi [12800*2048], g_v_lo [12800*2048];
__device__ __align__(256) __nv_bfloat16 g_q_hi [1792*1024],  g_q_lo [1792*1024];
__device__ __align__(256) __nv_bfloat16 g_a_hi [1280*1024],  g_a_lo [1280*1024];
__device__ __align__(256) __nv_bfloat16 g_Wv_hi[512*2048],   g_Wv_lo[512*2048];
__device__ __align__(256) __nv_bfloat16 g_Wq_hi[512*1024],   g_Wq_lo[512*1024];
__device__ __align__(256) __nv_bfloat16 g_Wa_hi[512*1024],   g_Wa_lo[512*1024];
__device__ __align__(256) __nv_bfloat16 g_Wvr_hi[512*512],   g_Wvr_lo[512*512];
__device__ __align__(256) __nv_bfloat16 g_Wqr_hi[512*512],   g_Wqr_lo[512*512];
__device__ __align__(256) __nv_bfloat16 g_War_hi[512*512],   g_War_lo[512*512];
__device__ __align__(256) __nv_bfloat16 g_vt_hi[12800*512],  g_vt_lo[12800*512];
__device__ __align__(256) __nv_bfloat16 g_qt_hi[1792*512],   g_qt_lo[1792*512];
__device__ __align__(256) __nv_bfloat16 g_at_hi[1280*512],   g_at_lo[1280*512];
__device__ __align__(256) __nv_bfloat16 g_v2_hi[12832*512],  g_v2_lo[12832*512];
__device__ __align__(256) float g_q2[1792*512];
__device__ __align__(256) float g_a2[1280*512];
__device__ __align__(256) __nv_bfloat16 g_tqaT_hi[128*CPAD*512];
__device__ __align__(256) __nv_bfloat16 g_tqaT_lo[128*CPAD*512];
__device__ __align__(256) float g_Tbar[8192];

// ---------------- PTX helpers ----------------
__device__ __forceinline__ uint32_t smem_u32(const void* p) {
    uint32_t a;
    asm("{ .reg .u64 t; cvta.to.shared.u64 t, %1; cvt.u32.u64 %0, t; }"
        : "=r"(a) : "l"(p));
    return a;
}
__device__ __forceinline__ void mma_bf16(float* c, const uint32_t* a,
                                         const uint32_t* b) {
    asm volatile(
        "mma.sync.aligned.m16n8k16.row.col.f32.bf16.bf16.f32 "
        "{%0,%1,%2,%3}, {%4,%5,%6,%7}, {%8,%9}, {%0,%1,%2,%3};"
        : "+f"(c[0]), "+f"(c[1]), "+f"(c[2]), "+f"(c[3])
        : "r"(a[0]), "r"(a[1]), "r"(a[2]), "r"(a[3]), "r"(b[0]), "r"(b[1]));
}
__device__ __forceinline__ void ldsm4(uint32_t* r, uint32_t addr) {
    asm volatile("ldmatrix.sync.aligned.m8n8.x4.shared.b16 {%0,%1,%2,%3}, [%4];"
                 : "=r"(r[0]), "=r"(r[1]), "=r"(r[2]), "=r"(r[3]) : "r"(addr));
}
__device__ __forceinline__ void cp16(uint32_t dst, const void* src) {
    asm volatile("cp.async.cg.shared.global [%0], [%1], 16;"
                 :: "r"(dst), "l"(src));
}
__device__ __forceinline__ void cp_commit() {
    asm volatile("cp.async.commit_group;");
}
template<int N>
__device__ __forceinline__ void cp_wait() {
    asm volatile("cp.async.wait_group %0;" :: "n"(N));
}
__device__ __forceinline__ uint32_t swz_off(int row, int c) {
    return (uint32_t)(row * 64 + ((c ^ ((row >> 1) & 3)) << 4));
}

// ---------------------------------------------------------------------------
// Splits: fp32 -> bf16 hi/lo, 8 elems/thread. Two launches (weights, acts)
// so grouped stage-1 lands at profiled launch position 4.
// ---------------------------------------------------------------------------
__device__ __forceinline__ void split8(const float* __restrict__ src,
                                       __nv_bfloat16* __restrict__ hi,
                                       __nv_bfloat16* __restrict__ lo, int i)
{
    float4 v0 = ((const float4*)src)[i * 2];
    float4 v1 = ((const float4*)src)[i * 2 + 1];
    float f[8] = {v0.x, v0.y, v0.z, v0.w, v1.x, v1.y, v1.z, v1.w};
    __nv_bfloat162 H[4], L[4];
    #pragma unroll
    for (int j = 0; j < 4; j++) {
        __nv_bfloat16 h0 = __float2bfloat16(f[j*2]);
        __nv_bfloat16 h1 = __float2bfloat16(f[j*2+1]);
        H[j] = {h0, h1};
        L[j] = {__float2bfloat16(f[j*2]   - __bfloat162float(h0)),
                __float2bfloat16(f[j*2+1] - __bfloat162float(h1))};
    }
    ((uint4*)hi)[i] = *(uint4*)H;
    ((uint4*)lo)[i] = *(uint4*)L;
}

// activations: v (3276800 u8-slots), q (229376), a (163840)
#define RA_Q   3276800
#define RA_A   3506176
#define RA_END 3670016
__global__ void act_split_kernel(const float* __restrict__ v,
                                 const float* __restrict__ q,
                                 const float* __restrict__ a)
{
    int gi = blockIdx.x * 256 + threadIdx.x;
    if (gi >= RA_END) return;
    if      (gi < RA_Q) split8(v, g_v_hi, g_v_lo, gi);
    else if (gi < RA_A) split8(q, g_q_hi, g_q_lo, gi - RA_Q);
    else                split8(a, g_a_hi, g_a_lo, gi - RA_A);
}

// weights: Wv 131072, Wq 65536, Wa 65536, Wvr/Wqr/War 32768 each
#define RW_WQ   131072
#define RW_WA   196608
#define RW_WVR  262144
#define RW_WQR  294912
#define RW_WAR  327680
#define RW_END  360448
__global__ void w_split_kernel(const float* __restrict__ Wv,
                               const float* __restrict__ Wq,
                               const float* __restrict__ Wa,
                               const float* __restrict__ Wvr,
                               const float* __restrict__ Wqr,
                               const float* __restrict__ War)
{
    int gi = blockIdx.x * 256 + threadIdx.x;
    if (gi >= RW_END) return;
    if      (gi < RW_WQ)  split8(Wv,  g_Wv_hi,  g_Wv_lo,  gi);
    else if (gi < RW_WA)  split8(Wq,  g_Wq_hi,  g_Wq_lo,  gi - RW_WQ);
    else if (gi < RW_WVR) split8(Wa,  g_Wa_hi,  g_Wa_lo,  gi - RW_WA);
    else if (gi < RW_WQR) split8(Wvr, g_Wvr_hi, g_Wvr_lo, gi - RW_WVR);
    else if (gi < RW_WAR) split8(Wqr, g_Wqr_hi, g_Wqr_lo, gi - RW_WQR);
    else                  split8(War, g_War_hi, g_War_lo, gi - RW_WAR);
}

// ---------------------------------------------------------------------------
// Tbar[x] = sum_r T[r*8192 + x]
// ---------------------------------------------------------------------------
__global__ void reduce_T_kernel(const float* __restrict__ T)
{
    int x = blockIdx.x * 256 + threadIdx.x;
    float s = 0.f;
    #pragma unroll
    for (int r = 0; r < RANK; r++) s += T[(size_t)r * 8192 + x];
    g_Tbar[x] = s;
}

// ---------------------------------------------------------------------------
// Grouped HMMA bf16x3 GEMM (term-major MMA ordering).
// Grid 496: [0,400) v tiles, [400,456) q, [456,496) a.
// BM=128, BN=128, BK=32, 8 warps (32x64), 3-stage cp.async, 2 CTAs/SM.
// ---------------------------------------------------------------------------
#define STAGE_SZ 32768
#define GEMM_SMEM (3 * STAGE_SZ)
#define OFF_AH 0
#define OFF_AL 8192
#define OFF_BH 16384
#define OFF_BL 24576
#define HN 512

template<int STAGE>
__global__ __launch_bounds__(256, 2)
void grouped_gemm(const float* __restrict__ bias_v,
                  const float* __restrict__ bias_q,
                  const float* __restrict__ bias_a)
{
    extern __shared__ char smem[];
    const uint32_t smb = smem_u32(smem);
    const int tid  = threadIdx.x;
    const int wid  = tid >> 5;
    const int lane = tid & 31;
    const int wm   = wid & 3;
    const int wn   = wid >> 2;
    const int id   = blockIdx.x;

    const __nv_bfloat16 *Ahi, *Alo, *Bhi, *Blo;
    const float* bias;
    __nv_bfloat16 *Chi = nullptr, *Clo = nullptr;
    float* Cf = nullptr;
    int K, pid;
    bool outbf;

    if (STAGE == 1) {
        outbf = true;
        if (id < 400) {
            pid = id;       Ahi = g_v_hi; Alo = g_v_lo;
            Bhi = g_Wv_hi;  Blo = g_Wv_lo; K = 2048; bias = bias_v;
            Chi = g_vt_hi;  Clo = g_vt_lo;
        } else if (id < 456) {
            pid = id - 400; Ahi = g_q_hi; Alo = g_q_lo;
            Bhi = g_Wq_hi;  Blo = g_Wq_lo; K = 1024; bias = bias_q;
            Chi = g_qt_hi;  Clo = g_qt_lo;
        } else {
            pid = id - 456; Ahi = g_a_hi; Alo = g_a_lo;
            Bhi = g_Wa_hi;  Blo = g_Wa_lo; K = 1024; bias = bias_a;
            Chi = g_at_hi;  Clo = g_at_lo;
        }
    } else {
        K = 512;
        if (id < 400) {
            pid = id;       Ahi = g_vt_hi; Alo = g_vt_lo;
            Bhi = g_Wvr_hi; Blo = g_Wvr_lo; bias = bias_v;
            Chi = g_v2_hi;  Clo = g_v2_lo; outbf = true;
        } else if (id < 456) {
            pid = id - 400; Ahi = g_qt_hi; Alo = g_qt_lo;
            Bhi = g_Wqr_hi; Blo = g_Wqr_lo; bias = bias_q;
            Cf = g_q2; outbf = false;
        } else {
            pid = id - 456; Ahi = g_at_hi; Alo = g_at_lo;
            Bhi = g_War_hi; Blo = g_War_lo; bias = bias_a;
            Cf = g_a2; outbf = false;
        }
    }
    const int bm = (pid >> 2) * 128;
    const int bn = (pid & 3) * 128;
    const int nchunks = K >> 5;

    auto load_stage = [&](int c) {
        const uint32_t sb = smb + (uint32_t)(c % 3) * STAGE_SZ;
        const int k0 = c << 5;
        #pragma unroll
        for (int i = 0; i < 2; i++) {
            int idx = tid + i * 256;
            int row = idx >> 2;
            int cc  = idx & 3;
            uint32_t so = swz_off(row, cc);
            size_t gA = (size_t)(bm + row) * K + k0 + cc * 8;
            size_t gB = (size_t)(bn + row) * K + k0 + cc * 8;
            cp16(sb + OFF_AH + so, Ahi + gA);
            cp16(sb + OFF_AL + so, Alo + gA);
            cp16(sb + OFF_BH + so, Bhi + gB);
            cp16(sb + OFF_BL + so, Blo + gB);
        }
    };

    float acc[2][8][4];
    #pragma unroll
    for (int mt = 0; mt < 2; mt++)
        #pragma unroll
        for (int nt = 0; nt < 8; nt++)
            #pragma unroll
            for (int i = 0; i < 4; i++) acc[mt][nt][i] = 0.f;

    const int a_r = (lane & 7) | (((lane >> 3) & 1) << 3);
    const int a_c = lane >> 4;
    const int b_r = (lane & 7) | ((lane >> 4) << 3);
    const int b_c = (lane >> 3) & 1;

    load_stage(0);
    cp_commit();
    load_stage(1);
    cp_commit();

    for (int c = 0; c < nchunks; c++) {
        cp_wait<1>();
        __syncthreads();

        if (c + 2 < nchunks) {
            load_stage(c + 2);
            cp_commit();
        } else {
            cp_commit();
        }

        const uint32_t sb = smb + (uint32_t)(c % 3) * STAGE_SZ;

        #pragma unroll
        for (int ks8 = 0; ks8 < 4; ks8 += 2) {
            // load ALL fragments for this ks8 first
            uint32_t af[2][2][4];   // [mt][hl]
            #pragma unroll
            for (int mt = 0; mt < 2; mt++) {
                int row = wm * 32 + mt * 16 + a_r;
                uint32_t so = swz_off(row, ks8 + a_c);
                ldsm4(af[mt][0], sb + OFF_AH + so);
                ldsm4(af[mt][1], sb + OFF_AL + so);
            }
            uint32_t bf[4][2][4];   // [nq][hl]
            #pragma unroll
            for (int nq = 0; nq < 4; nq++) {
                int row = wn * 64 + nq * 16 + b_r;
                uint32_t so = swz_off(row, ks8 + b_c);
                ldsm4(bf[nq][0], sb + OFF_BH + so);
                ldsm4(bf[nq][1], sb + OFF_BL + so);
            }
            // term-major: 16 independent accumulators between revisits
            #pragma unroll
            for (int mt = 0; mt < 2; mt++)
                #pragma unroll
                for (int nq = 0; nq < 4; nq++)
                    #pragma unroll
                    for (int h = 0; h < 2; h++)
                        mma_bf16(acc[mt][nq*2+h], af[mt][0], &bf[nq][0][h*2]);
            #pragma unroll
            for (int mt = 0; mt < 2; mt++)
                #pragma unroll
                for (int nq = 0; nq < 4; nq++)
                    #pragma unroll
                    for (int h = 0; h < 2; h++)
                        mma_bf16(acc[mt][nq*2+h], af[mt][0], &bf[nq][1][h*2]);
            #pragma unroll
            for (int mt = 0; mt < 2; mt++)
                #pragma unroll
                for (int nq = 0; nq < 4; nq++)
                    #pragma unroll
                    for (int h = 0; h < 2; h++)
                        mma_bf16(acc[mt][nq*2+h], af[mt][1], &bf[nq][0][h*2]);
        }
    }

    // epilogue: bias + relu
    const int g = lane >> 2;
    const int t = lane & 3;
    #pragma unroll
    for (int mt = 0; mt < 2; mt++) {
        #pragma unroll
        for (int nt = 0; nt < 8; nt++) {
            int row0 = bm + wm * 32 + mt * 16 + g;
            int row1 = row0 + 8;
            int col  = bn + wn * 64 + nt * 8 + t * 2;
            float bs0 = __ldg(bias + col), bs1 = __ldg(bias + col + 1);
            float v00 = fmaxf(acc[mt][nt][0] + bs0, 0.f);
            float v01 = fmaxf(acc[mt][nt][1] + bs1, 0.f);
            float v10 = fmaxf(acc[mt][nt][2] + bs0, 0.f);
            float v11 = fmaxf(acc[mt][nt][3] + bs1, 0.f);
            if (outbf) {
                __nv_bfloat16 h00 = __float2bfloat16(v00);
                __nv_bfloat16 h01 = __float2bfloat16(v01);
                __nv_bfloat16 h10 = __float2bfloat16(v10);
                __nv_bfloat16 h11 = __float2bfloat16(v11);
                __nv_bfloat162 H0 = {h00, h01}, H1 = {h10, h11};
                __nv_bfloat162 L0 = {
                    __float2bfloat16(v00 - __bfloat162float(h00)),
                    __float2bfloat16(v01 - __bfloat162float(h01))};
                __nv_bfloat162 L1 = {
                    __float2bfloat16(v10 - __bfloat162float(h10)),
                    __float2bfloat16(v11 - __bfloat162float(h11))};
                *(__nv_bfloat162*)(Chi + (size_t)row0 * HN + col) = H0;
                *(__nv_bfloat162*)(Clo + (size_t)row0 * HN + col) = L0;
                *(__nv_bfloat162*)(Chi + (size_t)row1 * HN + col) = H1;
                *(__nv_bfloat162*)(Clo + (size_t)row1 * HN + col) = L1;
            } else {
                *(float2*)(Cf + (size_t)row0 * HN + col) = make_float2(v00, v01);
                *(float2*)(Cf + (size_t)row1 * HN + col) = make_float2(v10, v11);
            }
        }
    }
}

// ---------------------------------------------------------------------------
// K7: per (b,n):  Tq = Tbar x_j q_,  Tqa = Tq x_k a_
// Writes TQA transposed as bf16 hi/lo: g_tqaT[b][c][n*16+ii], c=(q*10+a)*2+g
// ---------------------------------------------------------------------------
__global__ __launch_bounds__(256)
void tq_tqa_kernel()
{
    extern __shared__ float sm[];
    float* sT  = sm;               // 8192 (reused as sOut after step A)
    float* sQ  = sm + 8192;        // 224
    float* sA  = sm + 8416;        // 160
    float* sTq = sm + 8576;        // 7168

    const int n   = blockIdx.x;
    const int b   = blockIdx.y;
    const int tid = threadIdx.x;

    const float4* Tp = (const float4*)g_Tbar;
    for (int i = tid; i < 2048; i += 256) ((float4*)sT)[i] = Tp[i];

    if (tid < 56) {
        int q  = tid >> 2;
        int j4 = (tid & 3) << 2;
        *(float4*)&sQ[q * 16 + j4] =
            *(const float4*)(g_q2 + (size_t)(b * NQ + q) * 512 + n * 16 + j4);
    }
    if (tid >= 64 && tid < 104) {
        int t  = tid - 64;
        int a  = t >> 2;
        int k4 = (t & 3) << 2;
        *(float4*)&sA[a * 16 + k4] =
            *(const float4*)(g_a2 + (size_t)(b * NA + a) * 512 + n * 16 + k4);
    }
    __syncthreads();

    // step A: Tq[q,i,k,g]
    {
        const int i_ = tid >> 4;
        const int k_ = tid & 15;
        float accx[14], accy[14];
        #pragma unroll
        for (int q = 0; q < 14; q++) { accx[q] = 0.f; accy[q] = 0.f; }
        #pragma unroll
        for (int j = 0; j < 16; j++) {
            float2 t2 = *(const float2*)&sT[(((i_ * 16 + j) * 16) + k_) * 2];
            #pragma unroll
            for (int q = 0; q < 14; q++) {
                float qv = sQ[q * 16 + j];
                accx[q] = fmaf(t2.x, qv, accx[q]);
                accy[q] = fmaf(t2.y, qv, accy[q]);
            }
        }
        #pragma unroll
        for (int q = 0; q < 14; q++)
            *(float2*)&sTq[((q * 16 + i_) * 16 + k_) * 2] =
                make_float2(accx[q], accy[q]);
    }
    __syncthreads();

    // step B: contract with a_, stash transposed in sOut[ii][c]
    float* sOut = sT;   // [16][284]
    for (int t = tid; t < 2240; t += 256) {
        int ii  = t / 140;
        int rem = t - ii * 140;
        int q   = rem / 10;
        int a   = rem - q * 10;
        float sx = 0.f, sy = 0.f;
        #pragma unroll
        for (int k = 0; k < 16; k++) {
            float2 tq = *(const float2*)&sTq[((q * 16 + ii) * 16 + k) * 2];
            float  av = sA[a * 16 + k];
            sx = fmaf(tq.x, av, sx);
            sy = fmaf(tq.y, av, sy);
        }
        sOut[ii * 284 + rem * 2]     = sx;
        sOut[ii * 284 + rem * 2 + 1] = sy;
    }
    __syncthreads();

    for (int idx = tid; idx < 560; idx += 256) {
        int c    = idx >> 1;
        int half = idx & 1;
        __nv_bfloat162 H[4], L[4];
        #pragma unroll
        for (int j = 0; j < 4; j++) {
            float v0 = sOut[(half * 8 + j * 2)     * 284 + c];
            float v1 = sOut[(half * 8 + j * 2 + 1) * 284 + c];
            __nv_bfloat16 h0 = __float2bfloat16(v0);
            __nv_bfloat16 h1 = __float2bfloat16(v1);
            H[j] = {h0, h1};
            L[j] = {__float2bfloat16(v0 - __bfloat162float(h0)),
                    __float2bfloat16(v1 - __bfloat162float(h1))};
        }
        size_t off = ((size_t)b * CPAD + c) * 512 + n * 16 + half * 8;
        *(uint4*)(g_tqaT_hi + off) = *(uint4*)H;
        *(uint4*)(g_tqaT_lo + off) = *(uint4*)L;
    }
}

// ---------------------------------------------------------------------------
// K8 (HMMA): out[b][v][c] = sum_k V2[b*100+v][k] * TQA_T[b][c][k]
// BM=128 (100 valid), BN=96, BK=32, 256 threads, 3-stage pipeline,
// term-major MMA ordering.
// ---------------------------------------------------------------------------
#define K8_STAGE 28672
#define K8_SMEM  (3 * K8_STAGE)
#define K8_BH    16384
#define K8_BL    22528

__global__ __launch_bounds__(256, 2)
void k8_gemm(float* __restrict__ out)
{
    extern __shared__ char smem[];
    const uint32_t smb = smem_u32(smem);
    const int tid  = threadIdx.x;
    const int wid  = tid >> 5;
    const int lane = tid & 31;
    const int wm   = wid & 3;
    const int wn   = wid >> 2;
    const int bn   = blockIdx.x * 96;
    const int b    = blockIdx.y;

    const __nv_bfloat16* Ahi = g_v2_hi + (size_t)b * 100 * 512;
    const __nv_bfloat16* Alo = g_v2_lo + (size_t)b * 100 * 512;
    const __nv_bfloat16* Bhi = g_tqaT_hi + ((size_t)b * CPAD + bn) * 512;
    const __nv_bfloat16* Blo = g_tqaT_lo + ((size_t)b * CPAD + bn) * 512;

    auto load_stage = [&](int c) {
        const uint32_t sb = smb + (uint32_t)(c % 3) * K8_STAGE;
        const int k0 = c << 5;
        #pragma unroll
        for (int i = 0; i < 2; i++) {
            int idx = tid + i * 256;
            int row = idx >> 2, cc = idx & 3;
            uint32_t so = swz_off(row, cc);
            size_t g = (size_t)row * 512 + k0 + cc * 8;
            cp16(sb + OFF_AH + so, Ahi + g);
            cp16(sb + OFF_AL + so, Alo + g);
        }
        {
            int row = tid >> 2, cc = tid & 3;
            uint32_t so = swz_off(row, cc);
            size_t g = (size_t)row * 512 + k0 + cc * 8;
            cp16(sb + K8_BH + so, Bhi + g);
            cp16(sb + K8_BL + so, Blo + g);
        }
        if (tid < 128) {
            int idx = tid + 256;
            int row = idx >> 2, cc = idx & 3;
            uint32_t so = swz_off(row, cc);
            size_t g = (size_t)row * 512 + k0 + cc * 8;
            cp16(sb + K8_BH + so, Bhi + g);
            cp16(sb + K8_BL + so, Blo + g);
        }
    };

    float acc[2][6][4];
    #pragma unroll
    for (int mt = 0; mt < 2; mt++)
        #pragma unroll
        for (int nt = 0; nt < 6; nt++)
            #pragma unroll
            for (int i = 0; i < 4; i++) acc[mt][nt][i] = 0.f;

    const int a_r = (lane & 7) | (((lane >> 3) & 1) << 3);
    const int a_c = lane >> 4;
    const int b_r = (lane & 7) | ((lane >> 4) << 3);
    const int b_c = (lane >> 3) & 1;

    load_stage(0);
    cp_commit();
    load_stage(1);
    cp_commit();

    for (int c = 0; c < 16; c++) {
        cp_wait<1>();
        __syncthreads();

        if (c + 2 < 16) {
            load_stage(c + 2);
            cp_commit();
        } else {
            cp_commit();
        }

        const uint32_t sb = smb + (uint32_t)(c % 3) * K8_STAGE;

        #pragma unroll
        for (int ks8 = 0; ks8 < 4; ks8 += 2) {
            uint32_t af[2][2][4];
            #pragma unroll
            for (int mt = 0; mt < 2; mt++) {
                int row = wm * 32 + mt * 16 + a_r;
                uint32_t so = swz_off(row, ks8 + a_c);
                ldsm4(af[mt][0], sb + OFF_AH + so);
                ldsm4(af[mt][1], sb + OFF_AL + so);
            }
            uint32_t bf[3][2][4];
            #pragma unroll
            for (int nq = 0; nq < 3; nq++) {
                int row = wn * 48 + nq * 16 + b_r;
                uint32_t so = swz_off(row, ks8 + b_c);
                ldsm4(bf[nq][0], sb + K8_BH + so);
                ldsm4(bf[nq][1], sb + K8_BL + so);
            }
            #pragma unroll
            for (int mt = 0; mt < 2; mt++)
                #pragma unroll
                for (int nq = 0; nq < 3; nq++)
                    #pragma unroll
                    for (int h = 0; h < 2; h++)
                        mma_bf16(acc[mt][nq*2+h], af[mt][0], &bf[nq][0][h*2]);
            #pragma unroll
            for (int mt = 0; mt < 2; mt++)
                #pragma unroll
                for (int nq = 0; nq < 3; nq++)
                    #pragma unroll
                    for (int h = 0; h < 2; h++)
                        mma_bf16(acc[mt][nq*2+h], af[mt][0], &bf[nq][1][h*2]);
            #pragma unroll
            for (int mt = 0; mt < 2; mt++)
                #pragma unroll
                for (int nq = 0; nq < 3; nq++)
                    #pragma unroll
                    for (int h = 0; h < 2; h++)
                        mma_bf16(acc[mt][nq*2+h], af[mt][1], &bf[nq][0][h*2]);
        }
    }

    const int g = lane >> 2;
    const int t = lane & 3;
    #pragma unroll
    for (int mt = 0; mt < 2; mt++) {
        #pragma unroll
        for (int nt = 0; nt < 6; nt++) {
            int v0 = wm * 32 + mt * 16 + g;
            int v1 = v0 + 8;
            int cg = bn + wn * 48 + nt * 8 + t * 2;
            if (cg < QAG) {
                if (v0 < NV)
                    *(float2*)(out + ((size_t)b * NV + v0) * QAG + cg) =
                        make_float2(acc[mt][nt][0], acc[mt][nt][1]);
                if (v1 < NV)
                    *(float2*)(out + ((size_t)b * NV + v1) * QAG + cg) =
                        make_float2(acc[mt][nt][2], acc[mt][nt][3]);
            }
        }
    }
}

// ---------------------------------------------------------------------------
extern "C" void kernel_launch(void* const* d_in, const int* in_sizes, int n_in,
                              void* d_out, int out_size)
{
    const float* v   = (const float*)d_in[0];
    const float* q   = (const float*)d_in[1];
    const float* a   = (const float*)d_in[2];
    const float* Wv  = (const float*)d_in[3];
    const float* bv  = (const float*)d_in[4];
    const float* Wq  = (const float*)d_in[5];
    const float* bq  = (const float*)d_in[6];
    const float* Wa  = (const float*)d_in[7];
    const float* ba  = (const float*)d_in[8];
    const float* Wvr = (const float*)d_in[9];
    const float* bvr = (const float*)d_in[10];
    const float* Wqr = (const float*)d_in[11];
    const float* bqr = (const float*)d_in[12];
    const float* War = (const float*)d_in[13];
    const float* bar = (const float*)d_in[14];
    const float* T   = (const float*)d_in[15];
    float* out       = (float*)d_out;

    cudaFuncSetAttribute(grouped_gemm<1>, cudaFuncAttributeMaxDynamicSharedMemorySize, GEMM_SMEM);
    cudaFuncSetAttribute(grouped_gemm<2>, cudaFuncAttributeMaxDynamicSharedMemorySize, GEMM_SMEM);
    cudaFuncSetAttribute(tq_tqa_kernel, cudaFuncAttributeMaxDynamicSharedMemorySize, 62976);
    cudaFuncSetAttribute(k8_gemm, cudaFuncAttributeMaxDynamicSharedMemorySize, K8_SMEM);

    // 1: weight splits
    w_split_kernel<<<(RW_END + 255) / 256, 256>>>(Wv, Wq, Wa, Wvr, Wqr, War);
    // 2: activation splits
    act_split_kernel<<<(RA_END + 255) / 256, 256>>>(v, q, a);
    // 3: reduce T over rank
    reduce_T_kernel<<<32, 256>>>(T);

    // 4: grouped stage-1 (v + q + a modality projections) [ncu-profiled]
    grouped_gemm<1><<<496, 256, GEMM_SMEM>>>(bv, bq, ba);

    // 5: grouped stage-2 (rank projections)
    grouped_gemm<2><<<496, 256, GEMM_SMEM>>>(bvr, bqr, bar);

    // 6: Tucker core contraction -> TQA_T (bf16 hi/lo)
    tq_tqa_kernel<<<dim3(RANK, Bb), 256, 62976>>>();

    // 7: batched final GEMM -> output
    k8_gemm<<<dim3(3, Bb), 256, K8_SMEM>>>(out);
}